// round 3
// baseline (speedup 1.0000x reference)
#include <cuda_runtime.h>
#include <stdint.h>

#define NPTS 120000

// Scratch (static device memory; allocation-free at runtime).
static __device__ unsigned g_vmax[100663296];   // max G*Kc = 262144*384 (level 0)
static __device__ int      g_grid[691200];      // max polar grid 240*180*16
static __device__ int      g_p2p[NPTS];

// Order-preserving float<->uint monotone mapping (for atomicMax on floats).
// 0u is reserved: no real finite float encodes to 0, so 0u == "never written".
__device__ __forceinline__ unsigned enc_f(float f){
    unsigned u = (unsigned)__float_as_int(f);
    return (u & 0x80000000u) ? ~u : (u | 0x80000000u);
}
__device__ __forceinline__ float dec_f(unsigned u){
    unsigned v = (u & 0x80000000u) ? (u & 0x7fffffffu) : ~u;
    return __int_as_float((int)v);
}

__global__ void k_clear_u4(int n4){
    uint4 z = make_uint4(0u,0u,0u,0u);
    uint4* p = reinterpret_cast<uint4*>(g_vmax);
    for (int i = blockIdx.x*blockDim.x + threadIdx.x; i < n4; i += gridDim.x*blockDim.x)
        p[i] = z;
}

__global__ void k_grid_init(int n){
    for (int i = blockIdx.x*blockDim.x + threadIdx.x; i < n; i += gridDim.x*blockDim.x)
        g_grid[i] = 0x7fffffff;
}

__global__ void k_grid_scatter(const int* __restrict__ idx, int M, int P0, int P1, int P2){
    int m = blockIdx.x*blockDim.x + threadIdx.x;
    if (m >= M) return;
    int x = idx[m*4+1], y = idx[m*4+2], z = idx[m*4+3];
    if ((unsigned)x >= (unsigned)P0 || (unsigned)y >= (unsigned)P1 ||
        (unsigned)z >= (unsigned)P2) return;   // defensive: never OOB-atomic
    atomicMin(&g_grid[(x*P1+y)*P2 + z], m);
}

__device__ __forceinline__ void knn_check(int x,int y,int z,int qx,int qy,int qz,
                                          int P1,int P2,int& bd,int& bi){
    int c = g_grid[(x*P1+y)*P2 + z];
    if (c != 0x7fffffff){
        int dx = x-qx, dy = y-qy, dz = z-qz;
        int d = dx*dx + dy*dy + dz*dz;
        if (d < bd || (d == bd && c < bi)){ bd = d; bi = c; }
    }
}

// Exact 1-NN via expanding Chebyshev shells on the integer grid.
// Distances are exact ints (< 2^24) so this matches the reference fp32 argmin
// bit-for-bit, including first-index tie-breaking (atomicMin per cell +
// (d, idx) lexicographic compare across cells).
__global__ void k_knn(const float* __restrict__ pc,
                      int P0,int P1,int P2,
                      float pv0,float pv1,float pv2,
                      float c0,float c1,float c2){
    int i = blockIdx.x*blockDim.x + threadIdx.x;
    if (i >= NPTS) return;
    int qx = (int)floorf(__fdiv_rn(pc[i*3+0]-c0, pv0));
    int qy = (int)floorf(__fdiv_rn(pc[i*3+1]-c1, pv1));
    int qz = (int)floorf(__fdiv_rn(pc[i*3+2]-c2, pv2));
    int bd = 0x7fffffff, bi = 0x7fffffff;
    int rmax = P0 + P1 + P2;                 // covers queries just outside grid too
    for (int r = 0; r <= rmax; r++){
        if ((long long)r*r > (long long)bd) break;   // all cells with d <= bd scanned
        int x0 = max(qx-r, 0), x1 = min(qx+r, P0-1);
        int y0 = max(qy-r, 0), y1 = min(qy+r, P1-1);
        int z0 = max(qz-r, 0), z1 = min(qz+r, P2-1);
        for (int x = x0; x <= x1; x++){
            bool fx = (x == qx-r) || (x == qx+r);
            for (int y = y0; y <= y1; y++){
                bool fy = (y == qy-r) || (y == qy+r);
                if (fx | fy){
                    for (int z = z0; z <= z1; z++)
                        knn_check(x,y,z,qx,qy,qz,P1,P2,bd,bi);
                } else {
                    int za = qz - r;
                    if (za >= 0 && za < P2) knn_check(x,y,za,qx,qy,qz,P1,P2,bd,bi);
                    int zb = qz + r;
                    if (r > 0 && zb >= 0 && zb < P2) knn_check(x,y,zb,qx,qy,qz,P1,P2,bd,bi);
                }
            }
        }
    }
    g_p2p[i] = bi;
}

// Scatter-max concat(point_feat, vfeat[p2p]) into voxel rows. 2 points/block.
__global__ void k_scatter(const float* __restrict__ pf, const float* __restrict__ coord,
                          const float* __restrict__ vf, int C, int Kc, int M,
                          int D0,int D1,int D2,
                          float s0,float s1,float s2){
    int i = blockIdx.x * 2 + (threadIdx.x >> 7);   // 2 points per 256-thread block
    if (i >= NPTS) return;
    int lt = threadIdx.x & 127;
    int half = threadIdx.x >> 7;
    __shared__ int sh[2][2];
    if (lt == 0){
        float fx = __fdiv_rn(coord[i*3+0] + 25.6f, s0);
        float fy = __fdiv_rn(coord[i*3+1] + 25.6f, s1);
        float fz = __fdiv_rn(coord[i*3+2] + 2.0f,  s2);
        int x = min(max((int)floorf(fx), 0), D0-1);
        int y = min(max((int)floorf(fy), 0), D1-1);
        int z = min(max((int)floorf(fz), 0), D2-1);
        sh[half][0] = (x*D2 + z)*D1 + y;    // internal voxel ordering: y fastest
        sh[half][1] = g_p2p[i];
    }
    __syncthreads();
    unsigned* row = g_vmax + (size_t)sh[half][0] * (size_t)Kc;
    int p = sh[half][1];
    bool pvalid = ((unsigned)p < (unsigned)M);   // defensive
    for (int k = lt; k < Kc; k += 128){
        float v = (k < 256) ? pf[(size_t)i*256 + k]
                            : (pvalid ? vf[(size_t)p*C + (k-256)] : 0.0f);
        atomicMax(row + k, enc_f(v));
    }
}

// Dense SGEMM over all G voxel rows:  out = relu(A @ W + b), masked by occupancy,
// written directly in [C*D2, D0, D1] layout (coalesced via smem-staged transpose).
// BM=BN=128, BK=16, 256 threads, 8x8 micro-tiles.
__global__ void __launch_bounds__(256)
k_gemm(const float* __restrict__ W, const float* __restrict__ bias,
       float* __restrict__ out, size_t out_base,
       int Kc, int Nc, int D0, int D1, int D2){
    __shared__ float smem[16*132 + 16*128];
    float* As = smem;                 // As[kk][m], row stride 132 (pad: conflict-light)
    float* Bs = smem + 16*132;        // Bs[kk][n], row stride 128
    __shared__ int s_ob[128];
    __shared__ int s_oc[128];

    int t  = threadIdx.x;
    int ty = t >> 4, tx = t & 15;
    int row0 = blockIdx.x * 128;
    int col0 = blockIdx.y * 128;
    const unsigned* Abase = g_vmax + (size_t)row0 * (size_t)Kc;

    float acc[8][8];
    #pragma unroll
    for (int i = 0; i < 8; i++)
        #pragma unroll
        for (int j = 0; j < 8; j++) acc[i][j] = 0.0f;

    for (int k0 = 0; k0 < Kc; k0 += 16){
        #pragma unroll
        for (int j = 0; j < 2; j++){
            int e = t + j*256;            // [0,512)
            int m  = e >> 2;              // row in tile
            int kq = (e & 3) << 2;        // k quad
            uint4 u = *reinterpret_cast<const uint4*>(Abase + (size_t)m*Kc + (k0 + kq));
            As[(kq+0)*132 + m] = dec_f(u.x);
            As[(kq+1)*132 + m] = dec_f(u.y);
            As[(kq+2)*132 + m] = dec_f(u.z);
            As[(kq+3)*132 + m] = dec_f(u.w);
        }
        #pragma unroll
        for (int j = 0; j < 2; j++){
            int e = t + j*256;
            int kk = e >> 5;
            int n  = (e & 31) << 2;
            *reinterpret_cast<float4*>(Bs + kk*128 + n) =
                *reinterpret_cast<const float4*>(W + (size_t)(k0+kk)*Nc + col0 + n);
        }
        __syncthreads();
        #pragma unroll
        for (int kk = 0; kk < 16; kk++){
            float4 a0 = *reinterpret_cast<const float4*>(As + kk*132 + ty*8);
            float4 a1 = *reinterpret_cast<const float4*>(As + kk*132 + ty*8 + 4);
            float4 b0 = *reinterpret_cast<const float4*>(Bs + kk*128 + tx*8);
            float4 b1 = *reinterpret_cast<const float4*>(Bs + kk*128 + tx*8 + 4);
            float a[8] = {a0.x,a0.y,a0.z,a0.w,a1.x,a1.y,a1.z,a1.w};
            float b[8] = {b0.x,b0.y,b0.z,b0.w,b1.x,b1.y,b1.z,b1.w};
            #pragma unroll
            for (int i = 0; i < 8; i++)
                #pragma unroll
                for (int j = 0; j < 8; j++)
                    acc[i][j] = fmaf(a[i], b[j], acc[i][j]);
        }
        __syncthreads();
    }

    // Epilogue: occupancy + output offsets per row; bias+relu; transposed store.
    if (t < 128){
        int v  = row0 + t;
        int y  = v % D1;
        int zz = (v / D1) % D2;
        int xx = v / (D1*D2);
        s_ob[t] = (zz*D0 + xx)*D1 + y;                    // offset without channel
        s_oc[t] = (g_vmax[(size_t)v*(size_t)Kc] != 0u);   // occupied?
    }
    float bv[8];
    #pragma unroll
    for (int j = 0; j < 8; j++) bv[j] = bias[col0 + tx*8 + j];
    __syncthreads();

    size_t cstride = (size_t)D2 * D0 * D1;
    float* stage = smem;   // reuse As/Bs region: 32 cols x 128 rows, col-major
    #pragma unroll
    for (int s = 0; s < 4; s++){
        if ((tx >> 2) == s){
            int cl = (tx & 3) << 3;
            #pragma unroll
            for (int i = 0; i < 8; i++){
                int rr = ty*8 + i;
                int oc = s_oc[rr];
                #pragma unroll
                for (int j = 0; j < 8; j++){
                    float h = oc ? fmaxf(acc[i][j] + bv[j], 0.0f) : 0.0f;
                    stage[(cl+j)*128 + rr] = h;
                }
            }
        }
        __syncthreads();
        #pragma unroll
        for (int j = 0; j < 16; j++){
            int e  = t + j*256;          // [0,4096)
            int cc = e >> 7;
            int rr = e & 127;
            int c  = col0 + (s << 5) + cc;
            out[out_base + (size_t)c*cstride + s_ob[rr]] = stage[cc*128 + rr];
        }
        __syncthreads();
    }
}

extern "C" void kernel_launch(void* const* d_in, const int* in_sizes, int n_in,
                              void* d_out, int out_size){
    (void)in_sizes; (void)n_in; (void)out_size;
    const float* point_feat = (const float*)d_in[0];
    const float* p_coord    = (const float*)d_in[1];
    const float* coord      = (const float*)d_in[2];
    // setup_inputs() dict order: point_feat, p_coord, coord, batch,
    // then per level L: idxL, fL, WL, bL  (all created inside one loop iteration).
    const int*   idxs[3] = {(const int*)d_in[4],  (const int*)d_in[8],  (const int*)d_in[12]};
    const float* vfs[3]  = {(const float*)d_in[5],(const float*)d_in[9],(const float*)d_in[13]};
    const float* Ws[3]   = {(const float*)d_in[6],(const float*)d_in[10],(const float*)d_in[14]};
    const float* bs[3]   = {(const float*)d_in[7],(const float*)d_in[11],(const float*)d_in[15]};
    float* out = (float*)d_out;

    const int Ms[3]  = {40000, 15000, 5000};
    const int Cs[3]  = {128, 256, 512};
    const int P0s[3] = {240, 120, 60}, P1s[3] = {180, 90, 45}, P2s[3] = {16, 8, 4};
    const int D0s[3] = {128, 64, 32},  D1s[3] = {128, 64, 32}, D2s[3] = {16, 8, 4};

    const float pi  = 3.14159265358979f;
    const float r0c = 50.0f, r1c = pi + pi, r2c = 6.0f;       // CYL_MAX - CYL_MIN (fp32-exact)
    const float cr0 = 25.6f + 25.6f, cr1 = cr0, cr2 = 4.4f + 2.0f; // CART_MAX - CART_MIN

    size_t base = 0;
    for (int L = 0; L < 3; L++){
        int C = Cs[L], Kc = 256 + C;
        int P0 = P0s[L], P1 = P1s[L], P2 = P2s[L];
        int D0 = D0s[L], D1 = D1s[L], D2 = D2s[L];
        int G = D0 * D1 * D2;
        float sf  = (float)(2 << L);                 // 2, 4, 8
        float pv0 = r0c / (479.0f / sf);             // same fp32 op order as reference
        float pv1 = r1c / (359.0f / sf);
        float pv2 = r2c / (31.0f  / sf);
        float cv0 = cr0 / (float)D0;
        float cv1 = cr1 / (float)D1;
        float cv2 = cr2 / (float)D2;

        int n4 = (G * Kc) >> 2;
        int cgrid = min(2048, (n4 + 255) / 256);
        k_clear_u4<<<cgrid, 256>>>(n4);
        int P = P0 * P1 * P2;
        k_grid_init<<<(P + 255)/256, 256>>>(P);
        k_grid_scatter<<<(Ms[L] + 255)/256, 256>>>(idxs[L], Ms[L], P0, P1, P2);
        k_knn<<<(NPTS + 127)/128, 128>>>(p_coord, P0, P1, P2, pv0, pv1, pv2,
                                         0.0f, -pi, -4.0f);
        k_scatter<<<(NPTS + 1)/2, 256>>>(point_feat, coord, vfs[L], C, Kc, Ms[L],
                                         D0, D1, D2, cv0, cv1, cv2);
        dim3 gg(G/128, C/128);
        k_gemm<<<gg, 256>>>(Ws[L], bs[L], out, base, Kc, C, D0, D1, D2);
        base += (size_t)C * D2 * D0 * D1;
    }
}

// round 5
// speedup vs baseline: 1.1127x; 1.1127x over previous
#include <cuda_runtime.h>
#include <stdint.h>

#define NPTS 120000
#define R0PAD 120064                      // ceil(NPTS/128)*128 compact rows, level 0

// Region offsets inside g_vmax (u32 words)
#define OFF_L0 0ull
#define SZ_L0  (R0PAD*384ull)             // 46,104,576
#define OFF_L1 SZ_L0
#define SZ_L1  (32768ull*512ull)          // 16,777,216
#define OFF_L2 (OFF_L1 + SZ_L1)
#define SZ_L2  (4096ull*768ull)           // 3,145,728
#define VMAX_TOT (OFF_L2 + SZ_L2)         // 66,027,520 (u4-divisible)

// Polar grid regions (ints)
#define GOFF0 0
#define GOFF1 691200
#define GOFF2 777600
#define GRID_TOT 788400

#define OUT_L0_F 33554432ull              // 128*16*128*128 floats to pre-zero

static __device__ unsigned g_vmax[VMAX_TOT];
static __device__ int      g_grid[GRID_TOT];
static __device__ int      g_p2p[NPTS];
static __device__ int      g_vox[NPTS];
static __device__ int      g_map[262144];
static __device__ int      g_list[R0PAD];
static __device__ int      g_cnt;

__device__ __forceinline__ unsigned enc_f(float f){
    unsigned u = (unsigned)__float_as_int(f);
    return (u & 0x80000000u) ? ~u : (u | 0x80000000u);
}
__device__ __forceinline__ float dec_f(unsigned u){
    unsigned v = (u & 0x80000000u) ? (u & 0x7fffffffu) : ~u;
    return __int_as_float((int)v);
}

// Merged clear: whole g_vmax (all 3 level regions) + level-0 output region.
__global__ void k_clear_all(float* __restrict__ out){
    const int nv4 = (int)(VMAX_TOT >> 2);
    const int no4 = (int)(OUT_L0_F >> 2);
    uint4 z = make_uint4(0u,0u,0u,0u);
    uint4* pv = reinterpret_cast<uint4*>(g_vmax);
    uint4* po = reinterpret_cast<uint4*>(out);
    int stride = gridDim.x*blockDim.x;
    for (int i = blockIdx.x*blockDim.x + threadIdx.x; i < nv4; i += stride) pv[i] = z;
    for (int i = blockIdx.x*blockDim.x + threadIdx.x; i < no4; i += stride) po[i] = z;
}

// Merged init: all polar grids to INT_MAX, level-0 voxel map to -1, counter to 0.
__global__ void k_init_all(){
    int stride = gridDim.x*blockDim.x;
    for (int i = blockIdx.x*blockDim.x + threadIdx.x; i < GRID_TOT; i += stride)
        g_grid[i] = 0x7fffffff;
    for (int i = blockIdx.x*blockDim.x + threadIdx.x; i < 262144; i += stride)
        g_map[i] = -1;
    if (blockIdx.x == 0 && threadIdx.x == 0) g_cnt = 0;
}

__global__ void k_grid_scatter(const int* __restrict__ idx, int M, int goff,
                               int P0, int P1, int P2){
    int m = blockIdx.x*blockDim.x + threadIdx.x;
    if (m >= M) return;
    int x = idx[m*4+1], y = idx[m*4+2], z = idx[m*4+3];
    if ((unsigned)x >= (unsigned)P0 || (unsigned)y >= (unsigned)P1 ||
        (unsigned)z >= (unsigned)P2) return;
    atomicMin(&g_grid[goff + (x*P1+y)*P2 + z], m);
}

__device__ __forceinline__ void knn_check(const int* __restrict__ grid,
                                          int x,int y,int z,int qx,int qy,int qz,
                                          int P1,int P2,int& bd,int& bi){
    int c = grid[(x*P1+y)*P2 + z];
    if (c != 0x7fffffff){
        int dx = x-qx, dy = y-qy, dz = z-qz;
        int d = dx*dx + dy*dy + dz*dz;
        if (d < bd || (d == bd && c < bi)){ bd = d; bi = c; }
    }
}

// Exact 1-NN via expanding Chebyshev shells on the integer grid (see r1 notes).
__global__ void k_knn(const float* __restrict__ pc, int goff,
                      int P0,int P1,int P2,
                      float pv0,float pv1,float pv2,
                      float c0,float c1,float c2){
    int i = blockIdx.x*blockDim.x + threadIdx.x;
    if (i >= NPTS) return;
    const int* grid = g_grid + goff;
    int qx = (int)floorf(__fdiv_rn(pc[i*3+0]-c0, pv0));
    int qy = (int)floorf(__fdiv_rn(pc[i*3+1]-c1, pv1));
    int qz = (int)floorf(__fdiv_rn(pc[i*3+2]-c2, pv2));
    int bd = 0x7fffffff, bi = 0x7fffffff;
    int rmax = P0 + P1 + P2;
    for (int r = 0; r <= rmax; r++){
        if ((long long)r*r > (long long)bd) break;
        int x0 = max(qx-r, 0), x1 = min(qx+r, P0-1);
        int y0 = max(qy-r, 0), y1 = min(qy+r, P1-1);
        int z0 = max(qz-r, 0), z1 = min(qz+r, P2-1);
        for (int x = x0; x <= x1; x++){
            bool fx = (x == qx-r) || (x == qx+r);
            for (int y = y0; y <= y1; y++){
                bool fy = (y == qy-r) || (y == qy+r);
                if (fx | fy){
                    for (int z = z0; z <= z1; z++)
                        knn_check(grid,x,y,z,qx,qy,qz,P1,P2,bd,bi);
                } else {
                    int za = qz - r;
                    if (za >= 0 && za < P2) knn_check(grid,x,y,za,qx,qy,qz,P1,P2,bd,bi);
                    int zb = qz + r;
                    if (r > 0 && zb >= 0 && zb < P2) knn_check(grid,x,y,zb,qx,qy,qz,P1,P2,bd,bi);
                }
            }
        }
    }
    g_p2p[i] = bi;
}

__device__ __forceinline__ int vox_lin(const float* __restrict__ coord, int i,
                                       int D0,int D1,int D2,
                                       float s0,float s1,float s2){
    float fx = __fdiv_rn(coord[i*3+0] + 25.6f, s0);
    float fy = __fdiv_rn(coord[i*3+1] + 25.6f, s1);
    float fz = __fdiv_rn(coord[i*3+2] + 2.0f,  s2);
    int x = min(max((int)floorf(fx), 0), D0-1);
    int y = min(max((int)floorf(fy), 0), D1-1);
    int z = min(max((int)floorf(fz), 0), D2-1);
    return (x*D2 + z)*D1 + y;              // internal ordering: y fastest
}

// Level-0: compute voxel id per point, claim compact slots for occupied voxels.
__global__ void k_voxelize0(const float* __restrict__ coord,
                            int D0,int D1,int D2, float s0,float s1,float s2){
    int i = blockIdx.x*blockDim.x + threadIdx.x;
    if (i >= NPTS) return;
    int lin = vox_lin(coord, i, D0,D1,D2, s0,s1,s2);
    g_vox[i] = lin;
    int old = atomicCAS(&g_map[lin], -1, -2);
    if (old == -1){
        int slot = atomicAdd(&g_cnt, 1);
        g_map[lin] = slot;
        g_list[slot] = lin;
    }
}

// Level-0 scatter-max into compact rows. 2 points per 256-thread block.
__global__ void k_scatter0(const float* __restrict__ pf,
                           const float* __restrict__ vf, int C, int Kc, int M){
    int i = blockIdx.x * 2 + (threadIdx.x >> 7);
    if (i >= NPTS) return;
    int lt = threadIdx.x & 127;
    int row = g_map[g_vox[i]];
    int p = g_p2p[i];
    bool pvalid = ((unsigned)p < (unsigned)M);
    unsigned* r = g_vmax + OFF_L0 + (size_t)row * (size_t)Kc;
    for (int k = lt; k < Kc; k += 128){
        float v = (k < 256) ? pf[(size_t)i*256 + k]
                            : (pvalid ? vf[(size_t)p*C + (k-256)] : 0.0f);
        atomicMax(r + k, enc_f(v));
    }
}

// Dense scatter-max (levels 1,2).
__global__ void k_scatter(const float* __restrict__ pf, const float* __restrict__ coord,
                          const float* __restrict__ vf, int C, int Kc, int M,
                          size_t voff, int D0,int D1,int D2,
                          float s0,float s1,float s2){
    int i = blockIdx.x * 2 + (threadIdx.x >> 7);
    if (i >= NPTS) return;
    int lt = threadIdx.x & 127;
    int half = threadIdx.x >> 7;
    __shared__ int sh[2][2];
    if (lt == 0){
        sh[half][0] = vox_lin(coord, i, D0,D1,D2, s0,s1,s2);
        sh[half][1] = g_p2p[i];
    }
    __syncthreads();
    unsigned* row = g_vmax + voff + (size_t)sh[half][0] * (size_t)Kc;
    int p = sh[half][1];
    bool pvalid = ((unsigned)p < (unsigned)M);
    for (int k = lt; k < Kc; k += 128){
        float v = (k < 256) ? pf[(size_t)i*256 + k]
                            : (pvalid ? vf[(size_t)p*C + (k-256)] : 0.0f);
        atomicMax(row + k, enc_f(v));
    }
}

// SGEMM core shared by dense + compact epilogues.
// BM=BN=128, BK=16, 256 threads, 8x8 micro-tiles. COMPACT: rows are compact
// slots (offsets from g_list, stores guarded by cnt); else dense voxel rows.
template<bool COMPACT>
__global__ void __launch_bounds__(256)
k_gemm(const float* __restrict__ W, const float* __restrict__ bias,
       float* __restrict__ out, size_t out_base, size_t voff,
       int Kc, int Nc, int D0, int D1, int D2){
    int row0 = blockIdx.x * 128;
    int cnt = 0;
    if (COMPACT){
        cnt = *(volatile int*)&g_cnt;
        if (row0 >= cnt) return;
    }
    __shared__ float smem[16*132 + 16*128];
    float* As = smem;
    float* Bs = smem + 16*132;
    __shared__ int s_ob[128];
    __shared__ int s_oc[128];

    int t  = threadIdx.x;
    int ty = t >> 4, tx = t & 15;
    int col0 = blockIdx.y * 128;
    const unsigned* Abase = g_vmax + voff + (size_t)row0 * (size_t)Kc;

    float acc[8][8];
    #pragma unroll
    for (int i = 0; i < 8; i++)
        #pragma unroll
        for (int j = 0; j < 8; j++) acc[i][j] = 0.0f;

    for (int k0 = 0; k0 < Kc; k0 += 16){
        #pragma unroll
        for (int j = 0; j < 2; j++){
            int e = t + j*256;
            int m  = e >> 2;
            int kq = (e & 3) << 2;
            uint4 u = *reinterpret_cast<const uint4*>(Abase + (size_t)m*Kc + (k0 + kq));
            As[(kq+0)*132 + m] = dec_f(u.x);
            As[(kq+1)*132 + m] = dec_f(u.y);
            As[(kq+2)*132 + m] = dec_f(u.z);
            As[(kq+3)*132 + m] = dec_f(u.w);
        }
        #pragma unroll
        for (int j = 0; j < 2; j++){
            int e = t + j*256;
            int kk = e >> 5;
            int n  = (e & 31) << 2;
            *reinterpret_cast<float4*>(Bs + kk*128 + n) =
                *reinterpret_cast<const float4*>(W + (size_t)(k0+kk)*Nc + col0 + n);
        }
        __syncthreads();
        #pragma unroll
        for (int kk = 0; kk < 16; kk++){
            float4 a0 = *reinterpret_cast<const float4*>(As + kk*132 + ty*8);
            float4 a1 = *reinterpret_cast<const float4*>(As + kk*132 + ty*8 + 4);
            float4 b0 = *reinterpret_cast<const float4*>(Bs + kk*128 + tx*8);
            float4 b1 = *reinterpret_cast<const float4*>(Bs + kk*128 + tx*8 + 4);
            float a[8] = {a0.x,a0.y,a0.z,a0.w,a1.x,a1.y,a1.z,a1.w};
            float b[8] = {b0.x,b0.y,b0.z,b0.w,b1.x,b1.y,b1.z,b1.w};
            #pragma unroll
            for (int i = 0; i < 8; i++)
                #pragma unroll
                for (int j = 0; j < 8; j++)
                    acc[i][j] = fmaf(a[i], b[j], acc[i][j]);
        }
        __syncthreads();
    }

    if (t < 128){
        int v = row0 + t;
        int lin = COMPACT ? g_list[v] : v;
        int y  = lin % D1;
        int q  = lin / D1;
        int zz = q % D2;
        int xx = q / D2;
        s_ob[t] = (zz*D0 + xx)*D1 + y;
        s_oc[t] = COMPACT ? (v < cnt)
                          : (g_vmax[voff + (size_t)v*(size_t)Kc] != 0u);
    }
    float bv[8];
    #pragma unroll
    for (int j = 0; j < 8; j++) bv[j] = bias[col0 + tx*8 + j];
    __syncthreads();

    size_t cstride = (size_t)D2 * D0 * D1;
    float* stage = smem;
    #pragma unroll
    for (int s = 0; s < 4; s++){
        if ((tx >> 2) == s){
            int cl = (tx & 3) << 3;
            #pragma unroll
            for (int i = 0; i < 8; i++){
                int rr = ty*8 + i;
                int oc = s_oc[rr];
                #pragma unroll
                for (int j = 0; j < 8; j++){
                    float h = oc ? fmaxf(acc[i][j] + bv[j], 0.0f) : 0.0f;
                    stage[(cl+j)*128 + rr] = h;
                }
            }
        }
        __syncthreads();
        #pragma unroll
        for (int j = 0; j < 16; j++){
            int e  = t + j*256;
            int cc = e >> 7;
            int rr = e & 127;
            int c  = col0 + (s << 5) + cc;
            if (!COMPACT || s_oc[rr])      // compact: unoccupied slots pre-zeroed
                out[out_base + (size_t)c*cstride + s_ob[rr]] = stage[cc*128 + rr];
        }
        __syncthreads();
    }
}

extern "C" void kernel_launch(void* const* d_in, const int* in_sizes, int n_in,
                              void* d_out, int out_size){
    (void)in_sizes; (void)n_in; (void)out_size;
    const float* point_feat = (const float*)d_in[0];
    const float* p_coord    = (const float*)d_in[1];
    const float* coord      = (const float*)d_in[2];
    // setup_inputs() dict order: per level L: idxL, fL, WL, bL.
    const int*   idxs[3] = {(const int*)d_in[4],  (const int*)d_in[8],  (const int*)d_in[12]};
    const float* vfs[3]  = {(const float*)d_in[5],(const float*)d_in[9],(const float*)d_in[13]};
    const float* Ws[3]   = {(const float*)d_in[6],(const float*)d_in[10],(const float*)d_in[14]};
    const float* bs[3]   = {(const float*)d_in[7],(const float*)d_in[11],(const float*)d_in[15]};
    float* out = (float*)d_out;

    const int Ms[3]  = {40000, 15000, 5000};
    const int Cs[3]  = {128, 256, 512};
    const int P0s[3] = {240, 120, 60}, P1s[3] = {180, 90, 45}, P2s[3] = {16, 8, 4};
    const int D0s[3] = {128, 64, 32},  D1s[3] = {128, 64, 32}, D2s[3] = {16, 8, 4};
    const int goffs[3] = {GOFF0, GOFF1, GOFF2};
    const size_t voffs[3] = {OFF_L0, OFF_L1, OFF_L2};

    const float pi  = 3.14159265358979f;
    const float r0c = 50.0f, r1c = pi + pi, r2c = 6.0f;
    const float cr0 = 25.6f + 25.6f, cr1 = cr0, cr2 = 4.4f + 2.0f;

    k_clear_all<<<2048, 256>>>(out);
    k_init_all<<<1024, 256>>>();

    size_t base = 0;
    for (int L = 0; L < 3; L++){
        int C = Cs[L], Kc = 256 + C;
        int P0 = P0s[L], P1 = P1s[L], P2 = P2s[L];
        int D0 = D0s[L], D1 = D1s[L], D2 = D2s[L];
        int G = D0 * D1 * D2;
        float sf  = (float)(2 << L);
        float pv0 = r0c / (479.0f / sf);
        float pv1 = r1c / (359.0f / sf);
        float pv2 = r2c / (31.0f  / sf);
        float cv0 = cr0 / (float)D0;
        float cv1 = cr1 / (float)D1;
        float cv2 = cr2 / (float)D2;

        k_grid_scatter<<<(Ms[L] + 255)/256, 256>>>(idxs[L], Ms[L], goffs[L], P0, P1, P2);
        k_knn<<<(NPTS + 127)/128, 128>>>(p_coord, goffs[L], P0, P1, P2,
                                         pv0, pv1, pv2, 0.0f, -pi, -4.0f);
        if (L == 0){
            k_voxelize0<<<(NPTS + 255)/256, 256>>>(coord, D0,D1,D2, cv0,cv1,cv2);
            k_scatter0<<<(NPTS + 1)/2, 256>>>(point_feat, vfs[0], C, Kc, Ms[0]);
            dim3 gg(R0PAD/128, C/128);
            k_gemm<true><<<gg, 256>>>(Ws[0], bs[0], out, 0, OFF_L0, Kc, C, D0, D1, D2);
        } else {
            k_scatter<<<(NPTS + 1)/2, 256>>>(point_feat, coord, vfs[L], C, Kc, Ms[L],
                                             voffs[L], D0, D1, D2, cv0, cv1, cv2);
            dim3 gg(G/128, C/128);
            k_gemm<false><<<gg, 256>>>(Ws[L], bs[L], out, base, voffs[L], Kc, C, D0, D1, D2);
        }
        base += (size_t)C * D2 * D0 * D1;
    }
}

// round 6
// speedup vs baseline: 1.1997x; 1.0782x over previous
#include <cuda_runtime.h>
#include <stdint.h>

#define NPTS 120000
#define R0PAD 120064                      // ceil(NPTS/128)*128 compact rows, level 0

// Region offsets inside g_vmax (u32 words)
#define OFF_L0 0ull
#define SZ_L0  (R0PAD*384ull)
#define OFF_L1 SZ_L0
#define SZ_L1  (32768ull*512ull)
#define OFF_L2 (OFF_L1 + SZ_L1)
#define SZ_L2  (4096ull*768ull)
#define VMAX_TOT (OFF_L2 + SZ_L2)

// Polar grid regions (ints)
#define GOFF0 0
#define GOFF1 691200
#define GOFF2 777600
#define GRID_TOT 788400

#define OUT_L0_F 33554432ull              // level-0 output floats to pre-zero

static __device__ unsigned g_vmax[VMAX_TOT];
static __device__ int      g_grid[GRID_TOT];
static __device__ int      g_p2p[3*NPTS];
static __device__ int      g_vox[NPTS];
static __device__ int      g_map[262144];
static __device__ int      g_list[R0PAD];
static __device__ int      g_cnt;

struct KnnP { int goff, P0, P1, P2; float pv0, pv1, pv2; };
struct GsP  { int M, goff, P0, P1, P2; };

__device__ __forceinline__ unsigned enc_f(float f){
    unsigned u = (unsigned)__float_as_int(f);
    return (u & 0x80000000u) ? ~u : (u | 0x80000000u);
}
__device__ __forceinline__ float dec_f(unsigned u){
    unsigned v = (u & 0x80000000u) ? (u & 0x7fffffffu) : ~u;
    return __int_as_float((int)v);
}
__device__ __forceinline__ void split_tf32(float v, unsigned& hi, unsigned& lo){
    unsigned h; asm("cvt.rna.tf32.f32 %0, %1;" : "=r"(h) : "f"(v));
    float r = v - __uint_as_float(h);
    unsigned l; asm("cvt.rna.tf32.f32 %0, %1;" : "=r"(l) : "f"(r));
    hi = h; lo = l;
}
__device__ __forceinline__ void mma_tf32(float* d, const unsigned* a, const unsigned* b){
    asm volatile(
        "mma.sync.aligned.m16n8k8.row.col.f32.tf32.tf32.f32 "
        "{%0,%1,%2,%3}, {%4,%5,%6,%7}, {%8,%9}, {%0,%1,%2,%3};\n"
        : "+f"(d[0]), "+f"(d[1]), "+f"(d[2]), "+f"(d[3])
        : "r"(a[0]), "r"(a[1]), "r"(a[2]), "r"(a[3]), "r"(b[0]), "r"(b[1]));
}

__global__ void k_clear_all(float* __restrict__ out){
    const int nv4 = (int)(VMAX_TOT >> 2);
    const int no4 = (int)(OUT_L0_F >> 2);
    uint4 z = make_uint4(0u,0u,0u,0u);
    uint4* pv = reinterpret_cast<uint4*>(g_vmax);
    uint4* po = reinterpret_cast<uint4*>(out);
    int stride = gridDim.x*blockDim.x;
    for (int i = blockIdx.x*blockDim.x + threadIdx.x; i < nv4; i += stride) pv[i] = z;
    for (int i = blockIdx.x*blockDim.x + threadIdx.x; i < no4; i += stride) po[i] = z;
}

__global__ void k_init_all(){
    int stride = gridDim.x*blockDim.x;
    for (int i = blockIdx.x*blockDim.x + threadIdx.x; i < GRID_TOT; i += stride)
        g_grid[i] = 0x7fffffff;
    for (int i = blockIdx.x*blockDim.x + threadIdx.x; i < 262144; i += stride)
        g_map[i] = -1;
    if (blockIdx.x == 0 && threadIdx.x == 0) g_cnt = 0;
}

// All three levels' polar-grid scatters in one launch (blockIdx.y = level).
__global__ void k_grid_scatter_all(const int* __restrict__ i0, const int* __restrict__ i1,
                                   const int* __restrict__ i2, GsP s0, GsP s1, GsP s2){
    int L = blockIdx.y;
    const int* idx = (L==0) ? i0 : (L==1) ? i1 : i2;
    GsP s = (L==0) ? s0 : (L==1) ? s1 : s2;
    int m = blockIdx.x*blockDim.x + threadIdx.x;
    if (m >= s.M) return;
    int x = idx[m*4+1], y = idx[m*4+2], z = idx[m*4+3];
    if ((unsigned)x >= (unsigned)s.P0 || (unsigned)y >= (unsigned)s.P1 ||
        (unsigned)z >= (unsigned)s.P2) return;
    atomicMin(&g_grid[s.goff + (x*s.P1+y)*s.P2 + z], m);
}

__device__ __forceinline__ void knn_check(const int* __restrict__ grid,
                                          int x,int y,int z,int qx,int qy,int qz,
                                          int P1,int P2,int& bd,int& bi){
    int c = grid[(x*P1+y)*P2 + z];
    if (c != 0x7fffffff){
        int dx = x-qx, dy = y-qy, dz = z-qz;
        int d = dx*dx + dy*dy + dz*dz;
        if (d < bd || (d == bd && c < bi)){ bd = d; bi = c; }
    }
}

// Exact 1-NN, all 3 levels concurrent (blockIdx.y = level). See r1 notes for
// the exactness argument (integer distances < 2^24; first-index tie-break).
__global__ void k_knn_all(const float* __restrict__ pc, KnnP q0, KnnP q1, KnnP q2){
    int L = blockIdx.y;
    KnnP p = (L==0) ? q0 : (L==1) ? q1 : q2;
    int i = blockIdx.x*blockDim.x + threadIdx.x;
    if (i >= NPTS) return;
    const int* grid = g_grid + p.goff;
    int qx = (int)floorf(__fdiv_rn(pc[i*3+0]-0.0f,          p.pv0));
    int qy = (int)floorf(__fdiv_rn(pc[i*3+1]+3.14159274f,   p.pv1));  // -(-pi), fp32 of PI
    int qz = (int)floorf(__fdiv_rn(pc[i*3+2]+4.0f,          p.pv2));
    int bd = 0x7fffffff, bi = 0x7fffffff;
    int rmax = p.P0 + p.P1 + p.P2;
    for (int r = 0; r <= rmax; r++){
        if ((long long)r*r > (long long)bd) break;
        int x0 = max(qx-r, 0), x1 = min(qx+r, p.P0-1);
        int y0 = max(qy-r, 0), y1 = min(qy+r, p.P1-1);
        int z0 = max(qz-r, 0), z1 = min(qz+r, p.P2-1);
        for (int x = x0; x <= x1; x++){
            bool fx = (x == qx-r) || (x == qx+r);
            for (int y = y0; y <= y1; y++){
                bool fy = (y == qy-r) || (y == qy+r);
                if (fx | fy){
                    for (int z = z0; z <= z1; z++)
                        knn_check(grid,x,y,z,qx,qy,qz,p.P1,p.P2,bd,bi);
                } else {
                    int za = qz - r;
                    if (za >= 0 && za < p.P2) knn_check(grid,x,y,za,qx,qy,qz,p.P1,p.P2,bd,bi);
                    int zb = qz + r;
                    if (r > 0 && zb >= 0 && zb < p.P2) knn_check(grid,x,y,zb,qx,qy,qz,p.P1,p.P2,bd,bi);
                }
            }
        }
    }
    g_p2p[L*NPTS + i] = bi;
}

__device__ __forceinline__ int vox_lin(const float* __restrict__ coord, int i,
                                       int D0,int D1,int D2,
                                       float s0,float s1,float s2){
    float fx = __fdiv_rn(coord[i*3+0] + 25.6f, s0);
    float fy = __fdiv_rn(coord[i*3+1] + 25.6f, s1);
    float fz = __fdiv_rn(coord[i*3+2] + 2.0f,  s2);
    int x = min(max((int)floorf(fx), 0), D0-1);
    int y = min(max((int)floorf(fy), 0), D1-1);
    int z = min(max((int)floorf(fz), 0), D2-1);
    return (x*D2 + z)*D1 + y;              // internal ordering: y fastest
}

__global__ void k_voxelize0(const float* __restrict__ coord,
                            int D0,int D1,int D2, float s0,float s1,float s2){
    int i = blockIdx.x*blockDim.x + threadIdx.x;
    if (i >= NPTS) return;
    int lin = vox_lin(coord, i, D0,D1,D2, s0,s1,s2);
    g_vox[i] = lin;
    int old = atomicCAS(&g_map[lin], -1, -2);
    if (old == -1){
        int slot = atomicAdd(&g_cnt, 1);
        g_map[lin] = slot;
        g_list[slot] = lin;
    }
}

__global__ void k_scatter0(const float* __restrict__ pf,
                           const float* __restrict__ vf, int C, int Kc, int M){
    int i = blockIdx.x * 2 + (threadIdx.x >> 7);
    if (i >= NPTS) return;
    int lt = threadIdx.x & 127;
    int row = g_map[g_vox[i]];
    int p = g_p2p[i];                      // level 0
    bool pvalid = ((unsigned)p < (unsigned)M);
    unsigned* r = g_vmax + OFF_L0 + (size_t)row * (size_t)Kc;
    for (int k = lt; k < Kc; k += 128){
        float v = (k < 256) ? pf[(size_t)i*256 + k]
                            : (pvalid ? vf[(size_t)p*C + (k-256)] : 0.0f);
        atomicMax(r + k, enc_f(v));
    }
}

__global__ void k_scatter(const float* __restrict__ pf, const float* __restrict__ coord,
                          const float* __restrict__ vf, int C, int Kc, int M, int lvl,
                          size_t voff, int D0,int D1,int D2,
                          float s0,float s1,float s2){
    int i = blockIdx.x * 2 + (threadIdx.x >> 7);
    if (i >= NPTS) return;
    int lt = threadIdx.x & 127;
    int half = threadIdx.x >> 7;
    __shared__ int sh[2][2];
    if (lt == 0){
        sh[half][0] = vox_lin(coord, i, D0,D1,D2, s0,s1,s2);
        sh[half][1] = g_p2p[lvl*NPTS + i];
    }
    __syncthreads();
    unsigned* row = g_vmax + voff + (size_t)sh[half][0] * (size_t)Kc;
    int p = sh[half][1];
    bool pvalid = ((unsigned)p < (unsigned)M);
    for (int k = lt; k < Kc; k += 128){
        float v = (k < 256) ? pf[(size_t)i*256 + k]
                            : (pvalid ? vf[(size_t)p*C + (k-256)] : 0.0f);
        atomicMax(row + k, enc_f(v));
    }
}

// Split-TF32 tensor-core GEMM:  out = relu(A @ W + b), occupancy-masked,
// stored directly in [C*D2, D0, D1] layout. BM=BN=128, BK=16, 256 thr, 8 warps
// (2x4), warp tile 64x32, mma.sync.m16n8k8, 3-term split (err ~1e-7).
template<bool COMPACT>
__global__ void __launch_bounds__(256, 2)
k_gemm(const float* __restrict__ W, const float* __restrict__ bias,
       float* __restrict__ out, size_t out_base, size_t voff,
       int Kc, int Nc, int D0, int D1, int D2){
    int row0 = blockIdx.x * 128;
    int cnt = 0;
    if (COMPACT){
        cnt = *(volatile int*)&g_cnt;
        if (row0 >= cnt) return;
    }
    __shared__ unsigned smem_u[4*16*136];       // Ah|Al|Bh|Bl, stride 136
    __shared__ int s_ob[128];
    __shared__ int s_oc[128];
    unsigned* Ah = smem_u;
    unsigned* Al = smem_u + 2176;
    unsigned* Bh = smem_u + 4352;
    unsigned* Bl = smem_u + 6528;

    int t = threadIdx.x;
    int lane = t & 31, wid = t >> 5;
    int warp_m = wid & 1, warp_n = wid >> 1;    // 2 x 4 warp grid
    int g = lane >> 2, tg = lane & 3;
    int col0 = blockIdx.y * 128;
    const unsigned* Abase = g_vmax + voff + (size_t)row0 * (size_t)Kc;

    float acc[4][4][4];
    #pragma unroll
    for (int a = 0; a < 4; a++)
        #pragma unroll
        for (int b = 0; b < 4; b++)
            #pragma unroll
            for (int c = 0; c < 4; c++) acc[a][b][c] = 0.0f;

    for (int k0 = 0; k0 < Kc; k0 += 16){
        // Fill A (decode + split), transposed to [k][m]
        #pragma unroll
        for (int j = 0; j < 2; j++){
            int e = t + j*256;
            int m  = e >> 2;
            int kq = (e & 3) << 2;
            uint4 u = *reinterpret_cast<const uint4*>(Abase + (size_t)m*Kc + k0 + kq);
            unsigned h, l;
            split_tf32(dec_f(u.x), h, l); Ah[(kq+0)*136 + m] = h; Al[(kq+0)*136 + m] = l;
            split_tf32(dec_f(u.y), h, l); Ah[(kq+1)*136 + m] = h; Al[(kq+1)*136 + m] = l;
            split_tf32(dec_f(u.z), h, l); Ah[(kq+2)*136 + m] = h; Al[(kq+2)*136 + m] = l;
            split_tf32(dec_f(u.w), h, l); Ah[(kq+3)*136 + m] = h; Al[(kq+3)*136 + m] = l;
        }
        // Fill B (split), [k][n]
        #pragma unroll
        for (int j = 0; j < 2; j++){
            int e = t + j*256;
            int kk = e >> 5;
            int n  = (e & 31) << 2;
            float4 w = *reinterpret_cast<const float4*>(W + (size_t)(k0+kk)*Nc + col0 + n);
            uint4 hi, lo;
            split_tf32(w.x, hi.x, lo.x);
            split_tf32(w.y, hi.y, lo.y);
            split_tf32(w.z, hi.z, lo.z);
            split_tf32(w.w, hi.w, lo.w);
            *reinterpret_cast<uint4*>(Bh + kk*136 + n) = hi;
            *reinterpret_cast<uint4*>(Bl + kk*136 + n) = lo;
        }
        __syncthreads();
        #pragma unroll
        for (int ks = 0; ks < 2; ks++){
            int kk = ks << 3;
            unsigned bhf[4][2], blf[4][2];
            #pragma unroll
            for (int nt = 0; nt < 4; nt++){
                int n = warp_n*32 + nt*8 + g;
                bhf[nt][0] = Bh[(kk+tg)*136 + n];
                bhf[nt][1] = Bh[(kk+tg+4)*136 + n];
                blf[nt][0] = Bl[(kk+tg)*136 + n];
                blf[nt][1] = Bl[(kk+tg+4)*136 + n];
            }
            #pragma unroll
            for (int mt = 0; mt < 4; mt++){
                int r0 = warp_m*64 + mt*16 + g;
                unsigned ahf[4], alf[4];
                ahf[0] = Ah[(kk+tg)*136 + r0];
                ahf[1] = Ah[(kk+tg)*136 + r0 + 8];
                ahf[2] = Ah[(kk+tg+4)*136 + r0];
                ahf[3] = Ah[(kk+tg+4)*136 + r0 + 8];
                alf[0] = Al[(kk+tg)*136 + r0];
                alf[1] = Al[(kk+tg)*136 + r0 + 8];
                alf[2] = Al[(kk+tg+4)*136 + r0];
                alf[3] = Al[(kk+tg+4)*136 + r0 + 8];
                #pragma unroll
                for (int nt = 0; nt < 4; nt++){
                    mma_tf32(acc[mt][nt], ahf, bhf[nt]);
                    mma_tf32(acc[mt][nt], ahf, blf[nt]);
                    mma_tf32(acc[mt][nt], alf, bhf[nt]);
                }
            }
        }
        __syncthreads();
    }

    // Occupancy + output offsets per row
    if (t < 128){
        int v = row0 + t;
        int lin = COMPACT ? g_list[v] : v;
        int y  = lin % D1;
        int q  = lin / D1;
        int zz = q % D2;
        int xx = q / D2;
        s_ob[t] = (zz*D0 + xx)*D1 + y;
        s_oc[t] = COMPACT ? (v < cnt)
                          : (g_vmax[voff + (size_t)v*(size_t)Kc] != 0u);
    }
    __syncthreads();

    size_t cstride = (size_t)D2 * D0 * D1;
    float* stage = reinterpret_cast<float*>(smem_u);   // 32 x 128, stride 132
    #pragma unroll
    for (int s = 0; s < 4; s++){
        if (warp_n == s){
            #pragma unroll
            for (int mt = 0; mt < 4; mt++){
                int r0 = warp_m*64 + mt*16 + g;
                int r1 = r0 + 8;
                int oc0 = s_oc[r0], oc1 = s_oc[r1];
                #pragma unroll
                for (int nt = 0; nt < 4; nt++){
                    int cb = nt*8 + 2*tg;
                    float bv0 = bias[col0 + s*32 + cb];
                    float bv1 = bias[col0 + s*32 + cb + 1];
                    stage[(cb  )*132 + r0] = oc0 ? fmaxf(acc[mt][nt][0] + bv0, 0.0f) : 0.0f;
                    stage[(cb+1)*132 + r0] = oc0 ? fmaxf(acc[mt][nt][1] + bv1, 0.0f) : 0.0f;
                    stage[(cb  )*132 + r1] = oc1 ? fmaxf(acc[mt][nt][2] + bv0, 0.0f) : 0.0f;
                    stage[(cb+1)*132 + r1] = oc1 ? fmaxf(acc[mt][nt][3] + bv1, 0.0f) : 0.0f;
                }
            }
        }
        __syncthreads();
        #pragma unroll
        for (int j = 0; j < 16; j++){
            int e  = t + j*256;
            int cc = e >> 7;
            int rr = e & 127;
            int c  = col0 + (s << 5) + cc;
            if (!COMPACT || s_oc[rr])
                out[out_base + (size_t)c*cstride + s_ob[rr]] = stage[cc*132 + rr];
        }
        __syncthreads();
    }
}

extern "C" void kernel_launch(void* const* d_in, const int* in_sizes, int n_in,
                              void* d_out, int out_size){
    (void)in_sizes; (void)n_in; (void)out_size;
    const float* point_feat = (const float*)d_in[0];
    const float* p_coord    = (const float*)d_in[1];
    const float* coord      = (const float*)d_in[2];
    const int*   idxs[3] = {(const int*)d_in[4],  (const int*)d_in[8],  (const int*)d_in[12]};
    const float* vfs[3]  = {(const float*)d_in[5],(const float*)d_in[9],(const float*)d_in[13]};
    const float* Ws[3]   = {(const float*)d_in[6],(const float*)d_in[10],(const float*)d_in[14]};
    const float* bs[3]   = {(const float*)d_in[7],(const float*)d_in[11],(const float*)d_in[15]};
    float* out = (float*)d_out;

    const int Ms[3]  = {40000, 15000, 5000};
    const int Cs[3]  = {128, 256, 512};
    const int P0s[3] = {240, 120, 60}, P1s[3] = {180, 90, 45}, P2s[3] = {16, 8, 4};
    const int D0s[3] = {128, 64, 32},  D1s[3] = {128, 64, 32}, D2s[3] = {16, 8, 4};
    const int goffs[3] = {GOFF0, GOFF1, GOFF2};
    const size_t voffs[3] = {OFF_L0, OFF_L1, OFF_L2};

    const float pi  = 3.14159265358979f;
    const float r0c = 50.0f, r1c = pi + pi, r2c = 6.0f;
    const float cr0 = 25.6f + 25.6f, cr1 = cr0, cr2 = 4.4f + 2.0f;

    KnnP kp[3]; GsP gp[3];
    for (int L = 0; L < 3; L++){
        float sf = (float)(2 << L);
        kp[L].goff = goffs[L];
        kp[L].P0 = P0s[L]; kp[L].P1 = P1s[L]; kp[L].P2 = P2s[L];
        kp[L].pv0 = r0c / (479.0f / sf);
        kp[L].pv1 = r1c / (359.0f / sf);
        kp[L].pv2 = r2c / (31.0f  / sf);
        gp[L].M = Ms[L]; gp[L].goff = goffs[L];
        gp[L].P0 = P0s[L]; gp[L].P1 = P1s[L]; gp[L].P2 = P2s[L];
    }

    k_clear_all<<<2048, 256>>>(out);
    k_init_all<<<1024, 256>>>();
    k_grid_scatter_all<<<dim3((Ms[0]+255)/256, 3), 256>>>(idxs[0], idxs[1], idxs[2],
                                                          gp[0], gp[1], gp[2]);
    k_knn_all<<<dim3((NPTS+127)/128, 3), 128>>>(p_coord, kp[0], kp[1], kp[2]);

    size_t base = 0;
    for (int L = 0; L < 3; L++){
        int C = Cs[L], Kc = 256 + C;
        int D0 = D0s[L], D1 = D1s[L], D2 = D2s[L];
        int G = D0 * D1 * D2;
        float cv0 = cr0 / (float)D0;
        float cv1 = cr1 / (float)D1;
        float cv2 = cr2 / (float)D2;

        if (L == 0){
            k_voxelize0<<<(NPTS + 255)/256, 256>>>(coord, D0,D1,D2, cv0,cv1,cv2);
            k_scatter0<<<(NPTS + 1)/2, 256>>>(point_feat, vfs[0], C, Kc, Ms[0]);
            dim3 gg(R0PAD/128, C/128);
            k_gemm<true><<<gg, 256>>>(Ws[0], bs[0], out, 0, OFF_L0, Kc, C, D0, D1, D2);
        } else {
            k_scatter<<<(NPTS + 1)/2, 256>>>(point_feat, coord, vfs[L], C, Kc, Ms[L], L,
                                             voffs[L], D0, D1, D2, cv0, cv1, cv2);
            dim3 gg(G/128, C/128);
            k_gemm<false><<<gg, 256>>>(Ws[L], bs[L], out, base, voffs[L], Kc, C, D0, D1, D2);
        }
        base += (size_t)C * D2 * D0 * D1;
    }
}

// round 7
// speedup vs baseline: 1.4114x; 1.1765x over previous
#include <cuda_runtime.h>
#include <stdint.h>

#define NPTS 120000
#define R0PAD 120064

// Pooled-feature regions (float words)
#define OFF_L0 0ull
#define SZ_L0  (R0PAD*384ull)
#define OFF_L1 SZ_L0
#define SZ_L1  (32768ull*512ull)
#define OFF_L2 (OFF_L1 + SZ_L1)
#define SZ_L2  (4096ull*768ull)
#define VMAX_TOT (OFF_L2 + SZ_L2)

// Polar grid regions (ints)
#define GOFF0 0
#define GOFF1 691200
#define GOFF2 777600
#define GRID_TOT 788400

// Cartesian voxel-count regions (combined scan)
#define RO0 0
#define RO1 262144
#define RO2 294912
#define G_TOT 299008
#define G_PAD 300032          // 293 * 1024

#define OUT_L0_F 33554432ull  // level-0 output floats to pre-zero

static __device__ float    g_pool[VMAX_TOT];
static __device__ int      g_grid[GRID_TOT];
static __device__ int      g_p2p[3*NPTS];
static __device__ int      g_vox3[3*NPTS];
static __device__ int      g_pt[3*NPTS];
static __device__ int      g_cnts[G_PAD];
static __device__ int      g_start[G_PAD];
static __device__ int      g_cur[G_PAD];
static __device__ int      g_bsum[512];
static __device__ int      g_list[R0PAD];
static __device__ int      g_cnt;
static __device__ unsigned g_Wh[573440];
static __device__ unsigned g_Wl[573440];

struct KnnP { int goff, P0, P1, P2; float pv0, pv1, pv2; };
struct GsP  { int M, goff, P0, P1, P2; };
struct CntP { int ro, D0, D1, D2; float cv0, cv1, cv2; };

__device__ __forceinline__ void split_tf32(float v, unsigned& hi, unsigned& lo){
    unsigned h; asm("cvt.rna.tf32.f32 %0, %1;" : "=r"(h) : "f"(v));
    float r = v - __uint_as_float(h);
    unsigned l; asm("cvt.rna.tf32.f32 %0, %1;" : "=r"(l) : "f"(r));
    hi = h; lo = l;
}
__device__ __forceinline__ void mma_tf32(float* d, const unsigned* a, const unsigned* b){
    asm volatile(
        "mma.sync.aligned.m16n8k8.row.col.f32.tf32.tf32.f32 "
        "{%0,%1,%2,%3}, {%4,%5,%6,%7}, {%8,%9}, {%0,%1,%2,%3};\n"
        : "+f"(d[0]), "+f"(d[1]), "+f"(d[2]), "+f"(d[3])
        : "r"(a[0]), "r"(a[1]), "r"(a[2]), "r"(a[3]), "r"(b[0]), "r"(b[1]));
}

__global__ void k_clear_all(float* __restrict__ out){
    const int nv4 = (int)(VMAX_TOT >> 2);
    const int no4 = (int)(OUT_L0_F >> 2);
    uint4 z = make_uint4(0u,0u,0u,0u);
    uint4* pv = reinterpret_cast<uint4*>(g_pool);
    uint4* po = reinterpret_cast<uint4*>(out);
    int stride = gridDim.x*blockDim.x;
    for (int i = blockIdx.x*blockDim.x + threadIdx.x; i < nv4; i += stride) pv[i] = z;
    for (int i = blockIdx.x*blockDim.x + threadIdx.x; i < no4; i += stride) po[i] = z;
}

__global__ void k_init_all(){
    int stride = gridDim.x*blockDim.x;
    for (int i = blockIdx.x*blockDim.x + threadIdx.x; i < GRID_TOT; i += stride)
        g_grid[i] = 0x7fffffff;
    for (int i = blockIdx.x*blockDim.x + threadIdx.x; i < G_PAD; i += stride)
        g_cnts[i] = 0;
    if (blockIdx.x == 0 && threadIdx.x == 0) g_cnt = 0;
}

// Pre-split all three weight matrices into TF32 hi/lo (done once per launch).
__global__ void k_splitW(const float* __restrict__ w0, const float* __restrict__ w1,
                         const float* __restrict__ w2){
    int stride = gridDim.x*blockDim.x;
    for (int i = blockIdx.x*blockDim.x + threadIdx.x; i < 573440; i += stride){
        float v;
        if (i < 49152)       v = w0[i];
        else if (i < 180224) v = w1[i - 49152];
        else                 v = w2[i - 180224];
        split_tf32(v, g_Wh[i], g_Wl[i]);
    }
}

__global__ void k_grid_scatter_all(const int* __restrict__ i0, const int* __restrict__ i1,
                                   const int* __restrict__ i2, GsP s0, GsP s1, GsP s2){
    int L = blockIdx.y;
    const int* idx = (L==0) ? i0 : (L==1) ? i1 : i2;
    GsP s = (L==0) ? s0 : (L==1) ? s1 : s2;
    int m = blockIdx.x*blockDim.x + threadIdx.x;
    if (m >= s.M) return;
    int x = idx[m*4+1], y = idx[m*4+2], z = idx[m*4+3];
    if ((unsigned)x >= (unsigned)s.P0 || (unsigned)y >= (unsigned)s.P1 ||
        (unsigned)z >= (unsigned)s.P2) return;
    atomicMin(&g_grid[s.goff + (x*s.P1+y)*s.P2 + z], m);
}

__device__ __forceinline__ void knn_check(const int* __restrict__ grid,
                                          int x,int y,int z,int qx,int qy,int qz,
                                          int P1,int P2,int& bd,int& bi){
    int c = grid[(x*P1+y)*P2 + z];
    if (c != 0x7fffffff){
        int dx = x-qx, dy = y-qy, dz = z-qz;
        int d = dx*dx + dy*dy + dz*dz;
        if (d < bd || (d == bd && c < bi)){ bd = d; bi = c; }
    }
}

// Exact 1-NN, 3 levels concurrent (integer distances < 2^24; first-index ties).
__global__ void k_knn_all(const float* __restrict__ pc, KnnP q0, KnnP q1, KnnP q2){
    int L = blockIdx.y;
    KnnP p = (L==0) ? q0 : (L==1) ? q1 : q2;
    int i = blockIdx.x*blockDim.x + threadIdx.x;
    if (i >= NPTS) return;
    const int* grid = g_grid + p.goff;
    int qx = (int)floorf(__fdiv_rn(pc[i*3+0]-0.0f,        p.pv0));
    int qy = (int)floorf(__fdiv_rn(pc[i*3+1]+3.14159274f, p.pv1));
    int qz = (int)floorf(__fdiv_rn(pc[i*3+2]+4.0f,        p.pv2));
    int bd = 0x7fffffff, bi = 0x7fffffff;
    int rmax = p.P0 + p.P1 + p.P2;
    for (int r = 0; r <= rmax; r++){
        if ((long long)r*r > (long long)bd) break;
        int x0 = max(qx-r, 0), x1 = min(qx+r, p.P0-1);
        int y0 = max(qy-r, 0), y1 = min(qy+r, p.P1-1);
        int z0 = max(qz-r, 0), z1 = min(qz+r, p.P2-1);
        for (int x = x0; x <= x1; x++){
            bool fx = (x == qx-r) || (x == qx+r);
            for (int y = y0; y <= y1; y++){
                bool fy = (y == qy-r) || (y == qy+r);
                if (fx | fy){
                    for (int z = z0; z <= z1; z++)
                        knn_check(grid,x,y,z,qx,qy,qz,p.P1,p.P2,bd,bi);
                } else {
                    int za = qz - r;
                    if (za >= 0 && za < p.P2) knn_check(grid,x,y,za,qx,qy,qz,p.P1,p.P2,bd,bi);
                    int zb = qz + r;
                    if (r > 0 && zb >= 0 && zb < p.P2) knn_check(grid,x,y,zb,qx,qy,qz,p.P1,p.P2,bd,bi);
                }
            }
        }
    }
    g_p2p[L*NPTS + i] = bi;
}

// Per-point voxel ids + per-voxel counts, all 3 levels (blockIdx.y = level).
__global__ void k_count_all(const float* __restrict__ coord, CntP c0, CntP c1, CntP c2){
    int L = blockIdx.y;
    CntP c = (L==0) ? c0 : (L==1) ? c1 : c2;
    int i = blockIdx.x*blockDim.x + threadIdx.x;
    if (i >= NPTS) return;
    float fx = __fdiv_rn(coord[i*3+0] + 25.6f, c.cv0);
    float fy = __fdiv_rn(coord[i*3+1] + 25.6f, c.cv1);
    float fz = __fdiv_rn(coord[i*3+2] + 2.0f,  c.cv2);
    int x = min(max((int)floorf(fx), 0), c.D0-1);
    int y = min(max((int)floorf(fy), 0), c.D1-1);
    int z = min(max((int)floorf(fz), 0), c.D2-1);
    int lin = (x*c.D2 + z)*c.D1 + y;       // internal ordering: y fastest
    g_vox3[L*NPTS + i] = lin;
    atomicAdd(&g_cnts[c.ro + lin], 1);
}

// 3-kernel exclusive scan over the combined counts array (293 x 1024).
__global__ void k_scan1(){
    __shared__ int sh[256];
    int b = blockIdx.x, t = threadIdx.x;
    int base = b*1024 + t*4;
    int4 v = *reinterpret_cast<int4*>(&g_cnts[base]);
    int s = v.x+v.y+v.z+v.w;
    sh[t] = s;
    __syncthreads();
    #pragma unroll
    for (int off = 1; off < 256; off <<= 1){
        int val = (t >= off) ? sh[t-off] : 0;
        __syncthreads();
        sh[t] += val;
        __syncthreads();
    }
    int excl = sh[t] - s;
    g_start[base]   = excl;
    g_start[base+1] = excl + v.x;
    g_start[base+2] = excl + v.x + v.y;
    g_start[base+3] = excl + v.x + v.y + v.z;
    if (t == 255) g_bsum[b] = sh[255];
}
__global__ void k_scan2(){
    __shared__ int sh[512];
    int t = threadIdx.x;
    int v = (t < 293) ? g_bsum[t] : 0;
    sh[t] = v;
    __syncthreads();
    #pragma unroll
    for (int off = 1; off < 512; off <<= 1){
        int x = (t >= off) ? sh[t-off] : 0;
        __syncthreads();
        sh[t] += x;
        __syncthreads();
    }
    if (t < 293) g_bsum[t] = sh[t] - v;   // exclusive
}
__global__ void k_scan3(){
    int b = blockIdx.x, t = threadIdx.x;
    int add = g_bsum[b];
    int base = b*1024 + t*4;
    int4 v = *reinterpret_cast<int4*>(&g_start[base]);
    v.x += add; v.y += add; v.z += add; v.w += add;
    *reinterpret_cast<int4*>(&g_start[base]) = v;
    *reinterpret_cast<int4*>(&g_cur[base])   = v;
}

// Scatter point ids into per-voxel segments (global positions).
__global__ void k_ptscatter_all(int ro0, int ro1, int ro2){
    int L = blockIdx.y;
    int ro = (L==0) ? ro0 : (L==1) ? ro1 : ro2;
    int i = blockIdx.x*blockDim.x + threadIdx.x;
    if (i >= NPTS) return;
    int lin = g_vox3[L*NPTS + i];
    int pos = atomicAdd(&g_cur[ro + lin], 1);
    g_pt[pos] = i;
}

// Compact slot assignment for level 0 (one atomic per occupied voxel).
__global__ void k_slots0(){
    int lin = blockIdx.x*blockDim.x + threadIdx.x;
    if (lin >= 262144) return;
    if (g_cnts[RO0 + lin] > 0){
        int slot = atomicAdd(&g_cnt, 1);
        g_list[slot] = lin;
    }
}

// Gather-based max pooling: one 128-thread block per (occupied) voxel row.
template<bool COMPACT>
__global__ void __launch_bounds__(128)
k_pool(const float* __restrict__ pf, const float* __restrict__ vf,
       int L, int ro, int C, int Kc, size_t voff, int M){
    int row = blockIdx.x;
    int lin;
    if (COMPACT){
        if (row >= g_cnt) return;
        lin = g_list[row];
    } else lin = row;
    int s0 = g_start[ro + lin], s1 = g_start[ro + lin + 1];
    int n = s1 - s0;
    if (n <= 0) return;
    __shared__ int sp[128], spp[128];
    int t = threadIdx.x;
    float m[6];
    #pragma unroll
    for (int q = 0; q < 6; q++) m[q] = -__int_as_float(0x7f800000);  // -inf
    for (int c0 = 0; c0 < n; c0 += 128){
        int nc = min(128, n - c0);
        __syncthreads();
        if (t < nc){
            int i = g_pt[s0 + c0 + t];
            sp[t] = i;
            int p = g_p2p[L*NPTS + i];
            spp[t] = ((unsigned)p < (unsigned)M) ? p : 0;
        }
        __syncthreads();
        for (int j = 0; j < nc; j++){
            int i = sp[j], p = spp[j];
            int q = 0;
            for (int k = t; k < Kc; k += 128, q++){
                float v = (k < 256) ? pf[(size_t)i*256 + k]
                                    : vf[(size_t)p*C + (k-256)];
                m[q] = fmaxf(m[q], v);
            }
        }
    }
    float* dst = g_pool + voff + (size_t)row * (size_t)Kc;
    int q = 0;
    for (int k = t; k < Kc; k += 128, q++) dst[k] = m[q];
}

// Split-TF32 tensor-core GEMM: out = relu(A @ W + b), occupancy-masked,
// stored in [C*D2, D0, D1] layout. W pre-split; A split per tile.
template<bool COMPACT>
__global__ void __launch_bounds__(256, 2)
k_gemm(const float* __restrict__ bias,
       float* __restrict__ out, size_t out_base, size_t voff, int woff, int ro,
       int Kc, int Nc, int D0, int D1, int D2){
    int row0 = blockIdx.x * 128;
    int cnt = 0;
    if (COMPACT){
        cnt = *(volatile int*)&g_cnt;
        if (row0 >= cnt) return;
    }
    __shared__ unsigned smem_u[4*16*136];
    __shared__ int s_ob[128];
    __shared__ int s_oc[128];
    unsigned* Ah = smem_u;
    unsigned* Al = smem_u + 2176;
    unsigned* Bh = smem_u + 4352;
    unsigned* Bl = smem_u + 6528;

    int t = threadIdx.x;
    int lane = t & 31, wid = t >> 5;
    int warp_m = wid & 1, warp_n = wid >> 1;
    int g = lane >> 2, tg = lane & 3;
    int col0 = blockIdx.y * 128;
    const float* Abase = g_pool + voff + (size_t)row0 * (size_t)Kc;
    const unsigned* Whb = g_Wh + woff;
    const unsigned* Wlb = g_Wl + woff;

    float acc[4][4][4];
    #pragma unroll
    for (int a = 0; a < 4; a++)
        #pragma unroll
        for (int b = 0; b < 4; b++)
            #pragma unroll
            for (int c = 0; c < 4; c++) acc[a][b][c] = 0.0f;

    for (int k0 = 0; k0 < Kc; k0 += 16){
        #pragma unroll
        for (int j = 0; j < 2; j++){
            int e = t + j*256;
            int m  = e >> 2;
            int kq = (e & 3) << 2;
            float4 u = *reinterpret_cast<const float4*>(Abase + (size_t)m*Kc + k0 + kq);
            unsigned h, l;
            split_tf32(u.x, h, l); Ah[(kq+0)*136 + m] = h; Al[(kq+0)*136 + m] = l;
            split_tf32(u.y, h, l); Ah[(kq+1)*136 + m] = h; Al[(kq+1)*136 + m] = l;
            split_tf32(u.z, h, l); Ah[(kq+2)*136 + m] = h; Al[(kq+2)*136 + m] = l;
            split_tf32(u.w, h, l); Ah[(kq+3)*136 + m] = h; Al[(kq+3)*136 + m] = l;
        }
        #pragma unroll
        for (int j = 0; j < 2; j++){
            int e = t + j*256;
            int kk = e >> 5;
            int n  = (e & 31) << 2;
            size_t off = (size_t)(k0+kk)*Nc + col0 + n;
            *reinterpret_cast<uint4*>(Bh + kk*136 + n) =
                *reinterpret_cast<const uint4*>(Whb + off);
            *reinterpret_cast<uint4*>(Bl + kk*136 + n) =
                *reinterpret_cast<const uint4*>(Wlb + off);
        }
        __syncthreads();
        #pragma unroll
        for (int ks = 0; ks < 2; ks++){
            int kk = ks << 3;
            unsigned bhf[4][2], blf[4][2];
            #pragma unroll
            for (int nt = 0; nt < 4; nt++){
                int n = warp_n*32 + nt*8 + g;
                bhf[nt][0] = Bh[(kk+tg)*136 + n];
                bhf[nt][1] = Bh[(kk+tg+4)*136 + n];
                blf[nt][0] = Bl[(kk+tg)*136 + n];
                blf[nt][1] = Bl[(kk+tg+4)*136 + n];
            }
            #pragma unroll
            for (int mt = 0; mt < 4; mt++){
                int r0 = warp_m*64 + mt*16 + g;
                unsigned ahf[4], alf[4];
                ahf[0] = Ah[(kk+tg)*136 + r0];
                ahf[1] = Ah[(kk+tg)*136 + r0 + 8];
                ahf[2] = Ah[(kk+tg+4)*136 + r0];
                ahf[3] = Ah[(kk+tg+4)*136 + r0 + 8];
                alf[0] = Al[(kk+tg)*136 + r0];
                alf[1] = Al[(kk+tg)*136 + r0 + 8];
                alf[2] = Al[(kk+tg+4)*136 + r0];
                alf[3] = Al[(kk+tg+4)*136 + r0 + 8];
                #pragma unroll
                for (int nt = 0; nt < 4; nt++){
                    mma_tf32(acc[mt][nt], ahf, bhf[nt]);
                    mma_tf32(acc[mt][nt], ahf, blf[nt]);
                    mma_tf32(acc[mt][nt], alf, bhf[nt]);
                }
            }
        }
        __syncthreads();
    }

    if (t < 128){
        int v = row0 + t;
        int lin = COMPACT ? g_list[v] : v;
        int y  = lin % D1;
        int q  = lin / D1;
        int zz = q % D2;
        int xx = q / D2;
        s_ob[t] = (zz*D0 + xx)*D1 + y;
        s_oc[t] = COMPACT ? (v < cnt) : (g_cnts[ro + v] > 0);
    }
    __syncthreads();

    size_t cstride = (size_t)D2 * D0 * D1;
    float* stage = reinterpret_cast<float*>(smem_u);
    #pragma unroll
    for (int s = 0; s < 4; s++){
        if (warp_n == s){
            #pragma unroll
            for (int mt = 0; mt < 4; mt++){
                int r0 = warp_m*64 + mt*16 + g;
                int r1 = r0 + 8;
                int oc0 = s_oc[r0], oc1 = s_oc[r1];
                #pragma unroll
                for (int nt = 0; nt < 4; nt++){
                    int cb = nt*8 + 2*tg;
                    float bv0 = bias[col0 + s*32 + cb];
                    float bv1 = bias[col0 + s*32 + cb + 1];
                    stage[(cb  )*132 + r0] = oc0 ? fmaxf(acc[mt][nt][0] + bv0, 0.0f) : 0.0f;
                    stage[(cb+1)*132 + r0] = oc0 ? fmaxf(acc[mt][nt][1] + bv1, 0.0f) : 0.0f;
                    stage[(cb  )*132 + r1] = oc1 ? fmaxf(acc[mt][nt][2] + bv0, 0.0f) : 0.0f;
                    stage[(cb+1)*132 + r1] = oc1 ? fmaxf(acc[mt][nt][3] + bv1, 0.0f) : 0.0f;
                }
            }
        }
        __syncthreads();
        #pragma unroll
        for (int j = 0; j < 16; j++){
            int e  = t + j*256;
            int cc = e >> 7;
            int rr = e & 127;
            int c  = col0 + (s << 5) + cc;
            if (!COMPACT || s_oc[rr])
                out[out_base + (size_t)c*cstride + s_ob[rr]] = stage[cc*132 + rr];
        }
        __syncthreads();
    }
}

extern "C" void kernel_launch(void* const* d_in, const int* in_sizes, int n_in,
                              void* d_out, int out_size){
    (void)in_sizes; (void)n_in; (void)out_size;
    const float* point_feat = (const float*)d_in[0];
    const float* p_coord    = (const float*)d_in[1];
    const float* coord      = (const float*)d_in[2];
    const int*   idxs[3] = {(const int*)d_in[4],  (const int*)d_in[8],  (const int*)d_in[12]};
    const float* vfs[3]  = {(const float*)d_in[5],(const float*)d_in[9],(const float*)d_in[13]};
    const float* Ws[3]   = {(const float*)d_in[6],(const float*)d_in[10],(const float*)d_in[14]};
    const float* bs[3]   = {(const float*)d_in[7],(const float*)d_in[11],(const float*)d_in[15]};
    float* out = (float*)d_out;

    const int Ms[3]  = {40000, 15000, 5000};
    const int Cs[3]  = {128, 256, 512};
    const int P0s[3] = {240, 120, 60}, P1s[3] = {180, 90, 45}, P2s[3] = {16, 8, 4};
    const int D0s[3] = {128, 64, 32},  D1s[3] = {128, 64, 32}, D2s[3] = {16, 8, 4};
    const int goffs[3] = {GOFF0, GOFF1, GOFF2};
    const int ros[3]   = {RO0, RO1, RO2};
    const int woffs[3] = {0, 49152, 180224};
    const size_t voffs[3] = {OFF_L0, OFF_L1, OFF_L2};

    const float pi  = 3.14159265358979f;
    const float r0c = 50.0f, r1c = pi + pi, r2c = 6.0f;
    const float cr0 = 25.6f + 25.6f, cr1 = cr0, cr2 = 4.4f + 2.0f;

    KnnP kp[3]; GsP gp[3]; CntP cp[3];
    for (int L = 0; L < 3; L++){
        float sf = (float)(2 << L);
        kp[L].goff = goffs[L];
        kp[L].P0 = P0s[L]; kp[L].P1 = P1s[L]; kp[L].P2 = P2s[L];
        kp[L].pv0 = r0c / (479.0f / sf);
        kp[L].pv1 = r1c / (359.0f / sf);
        kp[L].pv2 = r2c / (31.0f  / sf);
        gp[L].M = Ms[L]; gp[L].goff = goffs[L];
        gp[L].P0 = P0s[L]; gp[L].P1 = P1s[L]; gp[L].P2 = P2s[L];
        cp[L].ro = ros[L];
        cp[L].D0 = D0s[L]; cp[L].D1 = D1s[L]; cp[L].D2 = D2s[L];
        cp[L].cv0 = cr0 / (float)D0s[L];
        cp[L].cv1 = cr1 / (float)D1s[L];
        cp[L].cv2 = cr2 / (float)D2s[L];
    }

    k_clear_all<<<2048, 256>>>(out);
    k_init_all<<<1024, 256>>>();
    k_splitW<<<560, 256>>>(Ws[0], Ws[1], Ws[2]);
    k_grid_scatter_all<<<dim3((Ms[0]+255)/256, 3), 256>>>(idxs[0], idxs[1], idxs[2],
                                                          gp[0], gp[1], gp[2]);
    k_knn_all<<<dim3((NPTS+127)/128, 3), 128>>>(p_coord, kp[0], kp[1], kp[2]);
    k_count_all<<<dim3((NPTS+255)/256, 3), 256>>>(coord, cp[0], cp[1], cp[2]);
    k_scan1<<<293, 256>>>();
    k_scan2<<<1, 512>>>();
    k_scan3<<<293, 256>>>();
    k_ptscatter_all<<<dim3((NPTS+255)/256, 3), 256>>>(RO0, RO1, RO2);
    k_slots0<<<262144/256, 256>>>();

    size_t base = 0;
    for (int L = 0; L < 3; L++){
        int C = Cs[L], Kc = 256 + C;
        int D0 = D0s[L], D1 = D1s[L], D2 = D2s[L];
        int G = D0 * D1 * D2;
        if (L == 0){
            k_pool<true><<<R0PAD, 128>>>(point_feat, vfs[0], 0, RO0, C, Kc, OFF_L0, Ms[0]);
            dim3 gg(R0PAD/128, C/128);
            k_gemm<true><<<gg, 256>>>(bs[0], out, 0, OFF_L0, woffs[0], RO0,
                                      Kc, C, D0, D1, D2);
        } else {
            k_pool<false><<<G, 128>>>(point_feat, vfs[L], L, ros[L], C, Kc, voffs[L], Ms[L]);
            dim3 gg(G/128, C/128);
            k_gemm<false><<<gg, 256>>>(bs[L], out, base, voffs[L], woffs[L], ros[L],
                                       Kc, C, D0, D1, D2);
        }
        base += (size_t)C * D2 * D0 * D1;
    }
}

// round 8
// speedup vs baseline: 1.6069x; 1.1385x over previous
#include <cuda_runtime.h>
#include <stdint.h>

#define NPTS 120000
#define R0PAD 120064

// Pooled-feature regions (float words)
#define OFF_L0 0ull
#define SZ_L0  (R0PAD*384ull)
#define OFF_L1 SZ_L0
#define SZ_L1  (32768ull*512ull)
#define OFF_L2 (OFF_L1 + SZ_L1)
#define SZ_L2  (4096ull*768ull)
#define VMAX_TOT (OFF_L2 + SZ_L2)

// Polar grid regions (ints)
#define GOFF0 0
#define GOFF1 691200
#define GOFF2 777600
#define GRID_TOT 788400

// Cartesian voxel-count regions (combined scan)
#define RO0 0
#define RO1 262144
#define RO2 294912
#define G_PAD 300032          // 293 * 1024

#define OUT_L0_F 33554432ull  // level-0 output floats to pre-zero

static __device__ float    g_pool[VMAX_TOT];
static __device__ int      g_grid[GRID_TOT];
static __device__ int      g_p2p[3*NPTS];
static __device__ int      g_vox3[3*NPTS];
static __device__ int      g_pt[3*NPTS];
static __device__ int      g_cnts[G_PAD];
static __device__ int      g_start[G_PAD];
static __device__ int      g_cur[G_PAD];
static __device__ int      g_bsum[512];
static __device__ int      g_list[R0PAD];
static __device__ int      g_cnt;
static __device__ unsigned g_Wh[573440];
static __device__ unsigned g_Wl[573440];

struct KnnP  { int goff, P0, P1, P2; float pv0, pv1, pv2; };
struct GsP   { int M, goff, P0, P1, P2; };
struct CntP  { int ro, D0, D1, D2; float cv0, cv1, cv2; };
struct PoolP { unsigned long long voff; int ro, C, Kc, M, L, nrows, compact; };
struct GemmP { unsigned long long out_base, voff; int woff, ro, Kc, Nc, D0, D1, D2, nb, nxb, compact; };

__device__ __forceinline__ void split_tf32(float v, unsigned& hi, unsigned& lo){
    unsigned h; asm("cvt.rna.tf32.f32 %0, %1;" : "=r"(h) : "f"(v));
    float r = v - __uint_as_float(h);
    unsigned l; asm("cvt.rna.tf32.f32 %0, %1;" : "=r"(l) : "f"(r));
    hi = h; lo = l;
}
__device__ __forceinline__ void mma_tf32(float* d, const unsigned* a, const unsigned* b){
    asm volatile(
        "mma.sync.aligned.m16n8k8.row.col.f32.tf32.tf32.f32 "
        "{%0,%1,%2,%3}, {%4,%5,%6,%7}, {%8,%9}, {%0,%1,%2,%3};\n"
        : "+f"(d[0]), "+f"(d[1]), "+f"(d[2]), "+f"(d[3])
        : "r"(a[0]), "r"(a[1]), "r"(a[2]), "r"(a[3]), "r"(b[0]), "r"(b[1]));
}

// Prep: zero L0 output region; init polar grids, counts, slot counter.
// (g_pool is intentionally NOT cleared: unoccupied rows are masked in the
// GEMM epilogue and accumulators are row-independent, so stale data there is
// output-invariant.)
__global__ void k_prep(float* __restrict__ out){
    const int no4 = (int)(OUT_L0_F >> 2);
    uint4 z = make_uint4(0u,0u,0u,0u);
    uint4* po = reinterpret_cast<uint4*>(out);
    int stride = gridDim.x*blockDim.x;
    int tid = blockIdx.x*blockDim.x + threadIdx.x;
    for (int i = tid; i < no4; i += stride) po[i] = z;
    for (int i = tid; i < GRID_TOT; i += stride) g_grid[i] = 0x7fffffff;
    for (int i = tid; i < G_PAD; i += stride) g_cnts[i] = 0;
    if (tid == 0) g_cnt = 0;
}

// Pre-split all three weight matrices into TF32 hi/lo (once per launch).
__global__ void k_splitW(const float* __restrict__ w0, const float* __restrict__ w1,
                         const float* __restrict__ w2){
    int stride = gridDim.x*blockDim.x;
    for (int i = blockIdx.x*blockDim.x + threadIdx.x; i < 573440; i += stride){
        float v;
        if (i < 49152)       v = w0[i];
        else if (i < 180224) v = w1[i - 49152];
        else                 v = w2[i - 180224];
        split_tf32(v, g_Wh[i], g_Wl[i]);
    }
}

__global__ void k_grid_scatter_all(const int* __restrict__ i0, const int* __restrict__ i1,
                                   const int* __restrict__ i2, GsP s0, GsP s1, GsP s2){
    int L = blockIdx.y;
    const int* idx = (L==0) ? i0 : (L==1) ? i1 : i2;
    GsP s = (L==0) ? s0 : (L==1) ? s1 : s2;
    int m = blockIdx.x*blockDim.x + threadIdx.x;
    if (m >= s.M) return;
    int x = idx[m*4+1], y = idx[m*4+2], z = idx[m*4+3];
    if ((unsigned)x >= (unsigned)s.P0 || (unsigned)y >= (unsigned)s.P1 ||
        (unsigned)z >= (unsigned)s.P2) return;
    atomicMin(&g_grid[s.goff + (x*s.P1+y)*s.P2 + z], m);
}

__device__ __forceinline__ void knn_check(const int* __restrict__ grid,
                                          int x,int y,int z,int qx,int qy,int qz,
                                          int P1,int P2,int& bd,int& bi){
    int c = grid[(x*P1+y)*P2 + z];
    if (c != 0x7fffffff){
        int dx = x-qx, dy = y-qy, dz = z-qz;
        int d = dx*dx + dy*dy + dz*dz;
        if (d < bd || (d == bd && c < bi)){ bd = d; bi = c; }
    }
}

// Exact 1-NN, 3 levels concurrent (integer distances < 2^24; first-index ties).
__global__ void k_knn_all(const float* __restrict__ pc, KnnP q0, KnnP q1, KnnP q2){
    int L = blockIdx.y;
    KnnP p = (L==0) ? q0 : (L==1) ? q1 : q2;
    int i = blockIdx.x*blockDim.x + threadIdx.x;
    if (i >= NPTS) return;
    const int* grid = g_grid + p.goff;
    int qx = (int)floorf(__fdiv_rn(pc[i*3+0]-0.0f,        p.pv0));
    int qy = (int)floorf(__fdiv_rn(pc[i*3+1]+3.14159274f, p.pv1));
    int qz = (int)floorf(__fdiv_rn(pc[i*3+2]+4.0f,        p.pv2));
    int bd = 0x7fffffff, bi = 0x7fffffff;
    int rmax = p.P0 + p.P1 + p.P2;
    for (int r = 0; r <= rmax; r++){
        if ((long long)r*r > (long long)bd) break;
        int x0 = max(qx-r, 0), x1 = min(qx+r, p.P0-1);
        int y0 = max(qy-r, 0), y1 = min(qy+r, p.P1-1);
        int z0 = max(qz-r, 0), z1 = min(qz+r, p.P2-1);
        for (int x = x0; x <= x1; x++){
            bool fx = (x == qx-r) || (x == qx+r);
            for (int y = y0; y <= y1; y++){
                bool fy = (y == qy-r) || (y == qy+r);
                if (fx | fy){
                    for (int z = z0; z <= z1; z++)
                        knn_check(grid,x,y,z,qx,qy,qz,p.P1,p.P2,bd,bi);
                } else {
                    int za = qz - r;
                    if (za >= 0 && za < p.P2) knn_check(grid,x,y,za,qx,qy,qz,p.P1,p.P2,bd,bi);
                    int zb = qz + r;
                    if (r > 0 && zb >= 0 && zb < p.P2) knn_check(grid,x,y,zb,qx,qy,qz,p.P1,p.P2,bd,bi);
                }
            }
        }
    }
    g_p2p[L*NPTS + i] = bi;
}

// Per-point voxel ids + per-voxel counts, all 3 levels (blockIdx.y = level).
__global__ void k_count_all(const float* __restrict__ coord, CntP c0, CntP c1, CntP c2){
    int L = blockIdx.y;
    CntP c = (L==0) ? c0 : (L==1) ? c1 : c2;
    int i = blockIdx.x*blockDim.x + threadIdx.x;
    if (i >= NPTS) return;
    float fx = __fdiv_rn(coord[i*3+0] + 25.6f, c.cv0);
    float fy = __fdiv_rn(coord[i*3+1] + 25.6f, c.cv1);
    float fz = __fdiv_rn(coord[i*3+2] + 2.0f,  c.cv2);
    int x = min(max((int)floorf(fx), 0), c.D0-1);
    int y = min(max((int)floorf(fy), 0), c.D1-1);
    int z = min(max((int)floorf(fz), 0), c.D2-1);
    int lin = (x*c.D2 + z)*c.D1 + y;       // internal ordering: y fastest
    g_vox3[L*NPTS + i] = lin;
    atomicAdd(&g_cnts[c.ro + lin], 1);
}

// 3-kernel exclusive scan over the combined counts array (293 x 1024).
__global__ void k_scan1(){
    __shared__ int sh[256];
    int b = blockIdx.x, t = threadIdx.x;
    int base = b*1024 + t*4;
    int4 v = *reinterpret_cast<int4*>(&g_cnts[base]);
    int s = v.x+v.y+v.z+v.w;
    sh[t] = s;
    __syncthreads();
    #pragma unroll
    for (int off = 1; off < 256; off <<= 1){
        int val = (t >= off) ? sh[t-off] : 0;
        __syncthreads();
        sh[t] += val;
        __syncthreads();
    }
    int excl = sh[t] - s;
    g_start[base]   = excl;
    g_start[base+1] = excl + v.x;
    g_start[base+2] = excl + v.x + v.y;
    g_start[base+3] = excl + v.x + v.y + v.z;
    if (t == 255) g_bsum[b] = sh[255];
}
__global__ void k_scan2(){
    __shared__ int sh[512];
    int t = threadIdx.x;
    int v = (t < 293) ? g_bsum[t] : 0;
    sh[t] = v;
    __syncthreads();
    #pragma unroll
    for (int off = 1; off < 512; off <<= 1){
        int x = (t >= off) ? sh[t-off] : 0;
        __syncthreads();
        sh[t] += x;
        __syncthreads();
    }
    if (t < 293) g_bsum[t] = sh[t] - v;   // exclusive
}
__global__ void k_scan3(){
    int b = blockIdx.x, t = threadIdx.x;
    int add = g_bsum[b];
    int base = b*1024 + t*4;
    int4 v = *reinterpret_cast<int4*>(&g_start[base]);
    v.x += add; v.y += add; v.z += add; v.w += add;
    *reinterpret_cast<int4*>(&g_start[base]) = v;
    *reinterpret_cast<int4*>(&g_cur[base])   = v;
}

// Scatter point ids into per-voxel segments (global positions).
__global__ void k_ptscatter_all(){
    int L = blockIdx.y;
    int ro = (L==0) ? RO0 : (L==1) ? RO1 : RO2;
    int i = blockIdx.x*blockDim.x + threadIdx.x;
    if (i >= NPTS) return;
    int lin = g_vox3[L*NPTS + i];
    int pos = atomicAdd(&g_cur[ro + lin], 1);
    g_pt[pos] = i;
}

// Compact slot assignment for level 0.
__global__ void k_slots0(){
    int lin = blockIdx.x*blockDim.x + threadIdx.x;
    if (lin >= 262144) return;
    if (g_cnts[RO0 + lin] > 0){
        int slot = atomicAdd(&g_cnt, 1);
        g_list[slot] = lin;
    }
}

// Gather-based max pooling, ALL levels in one launch.
// One 128-thread block per (occupied) voxel row.
__global__ void __launch_bounds__(128)
k_pool_all(const float* __restrict__ pf,
           const float* __restrict__ vf0, const float* __restrict__ vf1,
           const float* __restrict__ vf2,
           PoolP p0, PoolP p1, PoolP p2){
    int b = blockIdx.x;
    PoolP p; const float* vf;
    if (b < p0.nrows){ p = p0; vf = vf0; }
    else if (b < p0.nrows + p1.nrows){ p = p1; vf = vf1; b -= p0.nrows; }
    else { p = p2; vf = vf2; b -= p0.nrows + p1.nrows; }
    int row = b, lin;
    if (p.compact){
        if (row >= g_cnt) return;
        lin = g_list[row];
    } else lin = row;
    int s0 = g_start[p.ro + lin], s1 = g_start[p.ro + lin + 1];
    int n = s1 - s0;
    if (n <= 0) return;
    __shared__ int sp[128], spp[128];
    int t = threadIdx.x;
    float m[6];
    #pragma unroll
    for (int q = 0; q < 6; q++) m[q] = -__int_as_float(0x7f800000);
    for (int c0 = 0; c0 < n; c0 += 128){
        int nc = min(128, n - c0);
        __syncthreads();
        if (t < nc){
            int i = g_pt[s0 + c0 + t];
            sp[t] = i;
            int pp = g_p2p[p.L*NPTS + i];
            spp[t] = ((unsigned)pp < (unsigned)p.M) ? pp : 0;
        }
        __syncthreads();
        for (int j = 0; j < nc; j++){
            int i = sp[j], pp = spp[j];
            int q = 0;
            for (int k = t; k < p.Kc; k += 128, q++){
                float v = (k < 256) ? pf[(size_t)i*256 + k]
                                    : vf[(size_t)pp*p.C + (k-256)];
                m[q] = fmaxf(m[q], v);
            }
        }
    }
    float* dst = g_pool + p.voff + (size_t)row * (size_t)p.Kc;
    int q = 0;
    for (int k = t; k < p.Kc; k += 128, q++) dst[k] = m[q];
}

// Split-TF32 tensor-core GEMM, ALL levels in one launch (1D flattened grid).
// out = relu(A @ W + b), occupancy-masked, stored in [C*D2, D0, D1] layout.
__global__ void __launch_bounds__(256, 2)
k_gemm_all(const float* __restrict__ b0, const float* __restrict__ b1,
           const float* __restrict__ b2, float* __restrict__ out,
           GemmP q0, GemmP q1, GemmP q2){
    int b = blockIdx.x;
    GemmP p; const float* bias;
    if (b < q0.nb){ p = q0; bias = b0; }
    else if (b < q0.nb + q1.nb){ p = q1; bias = b1; b -= q0.nb; }
    else { p = q2; bias = b2; b -= q0.nb + q1.nb; }
    int bx = b % p.nxb, by = b / p.nxb;
    int row0 = bx * 128;
    int cnt = 0;
    if (p.compact){
        cnt = *(volatile int*)&g_cnt;
        if (row0 >= cnt) return;
    }
    __shared__ unsigned smem_u[4*16*136];
    __shared__ int s_ob[128];
    __shared__ int s_oc[128];
    unsigned* Ah = smem_u;
    unsigned* Al = smem_u + 2176;
    unsigned* Bh = smem_u + 4352;
    unsigned* Bl = smem_u + 6528;

    int t = threadIdx.x;
    int lane = t & 31, wid = t >> 5;
    int warp_m = wid & 1, warp_n = wid >> 1;
    int g = lane >> 2, tg = lane & 3;
    int col0 = by * 128;
    const float* Abase = g_pool + p.voff + (size_t)row0 * (size_t)p.Kc;
    const unsigned* Whb = g_Wh + p.woff;
    const unsigned* Wlb = g_Wl + p.woff;

    float acc[4][4][4];
    #pragma unroll
    for (int a = 0; a < 4; a++)
        #pragma unroll
        for (int c = 0; c < 4; c++)
            #pragma unroll
            for (int d = 0; d < 4; d++) acc[a][c][d] = 0.0f;

    for (int k0 = 0; k0 < p.Kc; k0 += 16){
        #pragma unroll
        for (int j = 0; j < 2; j++){
            int e = t + j*256;
            int m  = e >> 2;
            int kq = (e & 3) << 2;
            float4 u = *reinterpret_cast<const float4*>(Abase + (size_t)m*p.Kc + k0 + kq);
            unsigned h, l;
            split_tf32(u.x, h, l); Ah[(kq+0)*136 + m] = h; Al[(kq+0)*136 + m] = l;
            split_tf32(u.y, h, l); Ah[(kq+1)*136 + m] = h; Al[(kq+1)*136 + m] = l;
            split_tf32(u.z, h, l); Ah[(kq+2)*136 + m] = h; Al[(kq+2)*136 + m] = l;
            split_tf32(u.w, h, l); Ah[(kq+3)*136 + m] = h; Al[(kq+3)*136 + m] = l;
        }
        #pragma unroll
        for (int j = 0; j < 2; j++){
            int e = t + j*256;
            int kk = e >> 5;
            int n  = (e & 31) << 2;
            size_t off = (size_t)(k0+kk)*p.Nc + col0 + n;
            *reinterpret_cast<uint4*>(Bh + kk*136 + n) =
                *reinterpret_cast<const uint4*>(Whb + off);
            *reinterpret_cast<uint4*>(Bl + kk*136 + n) =
                *reinterpret_cast<const uint4*>(Wlb + off);
        }
        __syncthreads();
        #pragma unroll
        for (int ks = 0; ks < 2; ks++){
            int kk = ks << 3;
            unsigned bhf[4][2], blf[4][2];
            #pragma unroll
            for (int nt = 0; nt < 4; nt++){
                int n = warp_n*32 + nt*8 + g;
                bhf[nt][0] = Bh[(kk+tg)*136 + n];
                bhf[nt][1] = Bh[(kk+tg+4)*136 + n];
                blf[nt][0] = Bl[(kk+tg)*136 + n];
                blf[nt][1] = Bl[(kk+tg+4)*136 + n];
            }
            #pragma unroll
            for (int mt = 0; mt < 4; mt++){
                int r0 = warp_m*64 + mt*16 + g;
                unsigned ahf[4], alf[4];
                ahf[0] = Ah[(kk+tg)*136 + r0];
                ahf[1] = Ah[(kk+tg)*136 + r0 + 8];
                ahf[2] = Ah[(kk+tg+4)*136 + r0];
                ahf[3] = Ah[(kk+tg+4)*136 + r0 + 8];
                alf[0] = Al[(kk+tg)*136 + r0];
                alf[1] = Al[(kk+tg)*136 + r0 + 8];
                alf[2] = Al[(kk+tg+4)*136 + r0];
                alf[3] = Al[(kk+tg+4)*136 + r0 + 8];
                #pragma unroll
                for (int nt = 0; nt < 4; nt++){
                    mma_tf32(acc[mt][nt], ahf, bhf[nt]);
                    mma_tf32(acc[mt][nt], ahf, blf[nt]);
                    mma_tf32(acc[mt][nt], alf, bhf[nt]);
                }
            }
        }
        __syncthreads();
    }

    if (t < 128){
        int v = row0 + t;
        int lin = p.compact ? g_list[v] : v;
        int y  = lin % p.D1;
        int q  = lin / p.D1;
        int zz = q % p.D2;
        int xx = q / p.D2;
        s_ob[t] = (zz*p.D0 + xx)*p.D1 + y;
        s_oc[t] = p.compact ? (v < cnt) : (g_cnts[p.ro + v] > 0);
    }
    __syncthreads();

    size_t cstride = (size_t)p.D2 * p.D0 * p.D1;
    float* stage = reinterpret_cast<float*>(smem_u);
    #pragma unroll
    for (int s = 0; s < 4; s++){
        if (warp_n == s){
            #pragma unroll
            for (int mt = 0; mt < 4; mt++){
                int r0 = warp_m*64 + mt*16 + g;
                int r1 = r0 + 8;
                int oc0 = s_oc[r0], oc1 = s_oc[r1];
                #pragma unroll
                for (int nt = 0; nt < 4; nt++){
                    int cb = nt*8 + 2*tg;
                    float bv0 = bias[col0 + s*32 + cb];
                    float bv1 = bias[col0 + s*32 + cb + 1];
                    stage[(cb  )*132 + r0] = oc0 ? fmaxf(acc[mt][nt][0] + bv0, 0.0f) : 0.0f;
                    stage[(cb+1)*132 + r0] = oc0 ? fmaxf(acc[mt][nt][1] + bv1, 0.0f) : 0.0f;
                    stage[(cb  )*132 + r1] = oc1 ? fmaxf(acc[mt][nt][2] + bv0, 0.0f) : 0.0f;
                    stage[(cb+1)*132 + r1] = oc1 ? fmaxf(acc[mt][nt][3] + bv1, 0.0f) : 0.0f;
                }
            }
        }
        __syncthreads();
        #pragma unroll
        for (int j = 0; j < 16; j++){
            int e  = t + j*256;
            int cc = e >> 7;
            int rr = e & 127;
            int c  = col0 + (s << 5) + cc;
            if (!p.compact || s_oc[rr])
                out[p.out_base + (size_t)c*cstride + s_ob[rr]] = stage[cc*132 + rr];
        }
        __syncthreads();
    }
}

extern "C" void kernel_launch(void* const* d_in, const int* in_sizes, int n_in,
                              void* d_out, int out_size){
    (void)in_sizes; (void)n_in; (void)out_size;
    const float* point_feat = (const float*)d_in[0];
    const float* p_coord    = (const float*)d_in[1];
    const float* coord      = (const float*)d_in[2];
    const int*   idxs[3] = {(const int*)d_in[4],  (const int*)d_in[8],  (const int*)d_in[12]};
    const float* vfs[3]  = {(const float*)d_in[5],(const float*)d_in[9],(const float*)d_in[13]};
    const float* Ws[3]   = {(const float*)d_in[6],(const float*)d_in[10],(const float*)d_in[14]};
    const float* bs[3]   = {(const float*)d_in[7],(const float*)d_in[11],(const float*)d_in[15]};
    float* out = (float*)d_out;

    const int Ms[3]  = {40000, 15000, 5000};
    const int Cs[3]  = {128, 256, 512};
    const int P0s[3] = {240, 120, 60}, P1s[3] = {180, 90, 45}, P2s[3] = {16, 8, 4};
    const int D0s[3] = {128, 64, 32},  D1s[3] = {128, 64, 32}, D2s[3] = {16, 8, 4};
    const int goffs[3] = {GOFF0, GOFF1, GOFF2};
    const int ros[3]   = {RO0, RO1, RO2};
    const int woffs[3] = {0, 49152, 180224};
    const size_t voffs[3] = {OFF_L0, OFF_L1, OFF_L2};
    const int nrows[3] = {R0PAD, 32768, 4096};

    const float pi  = 3.14159265358979f;
    const float r0c = 50.0f, r1c = pi + pi, r2c = 6.0f;
    const float cr0 = 25.6f + 25.6f, cr1 = cr0, cr2 = 4.4f + 2.0f;

    KnnP kp[3]; GsP gp[3]; CntP cp[3]; PoolP pp[3]; GemmP gm[3];
    size_t base = 0;
    for (int L = 0; L < 3; L++){
        float sf = (float)(2 << L);
        kp[L].goff = goffs[L];
        kp[L].P0 = P0s[L]; kp[L].P1 = P1s[L]; kp[L].P2 = P2s[L];
        kp[L].pv0 = r0c / (479.0f / sf);
        kp[L].pv1 = r1c / (359.0f / sf);
        kp[L].pv2 = r2c / (31.0f  / sf);
        gp[L].M = Ms[L]; gp[L].goff = goffs[L];
        gp[L].P0 = P0s[L]; gp[L].P1 = P1s[L]; gp[L].P2 = P2s[L];
        cp[L].ro = ros[L];
        cp[L].D0 = D0s[L]; cp[L].D1 = D1s[L]; cp[L].D2 = D2s[L];
        cp[L].cv0 = cr0 / (float)D0s[L];
        cp[L].cv1 = cr1 / (float)D1s[L];
        cp[L].cv2 = cr2 / (float)D2s[L];
        pp[L].voff = voffs[L]; pp[L].ro = ros[L];
        pp[L].C = Cs[L]; pp[L].Kc = 256 + Cs[L]; pp[L].M = Ms[L];
        pp[L].L = L; pp[L].nrows = nrows[L]; pp[L].compact = (L == 0);
        gm[L].out_base = base; gm[L].voff = voffs[L];
        gm[L].woff = woffs[L]; gm[L].ro = ros[L];
        gm[L].Kc = 256 + Cs[L]; gm[L].Nc = Cs[L];
        gm[L].D0 = D0s[L]; gm[L].D1 = D1s[L]; gm[L].D2 = D2s[L];
        gm[L].nxb = nrows[L] / 128;
        gm[L].nb  = gm[L].nxb * (Cs[L] / 128);
        gm[L].compact = (L == 0);
        base += (size_t)Cs[L] * D2s[L] * D0s[L] * D1s[L];
    }

    k_prep<<<1024, 256>>>(out);
    k_splitW<<<560, 256>>>(Ws[0], Ws[1], Ws[2]);
    k_grid_scatter_all<<<dim3((Ms[0]+255)/256, 3), 256>>>(idxs[0], idxs[1], idxs[2],
                                                          gp[0], gp[1], gp[2]);
    k_knn_all<<<dim3((NPTS+127)/128, 3), 128>>>(p_coord, kp[0], kp[1], kp[2]);
    k_count_all<<<dim3((NPTS+255)/256, 3), 256>>>(coord, cp[0], cp[1], cp[2]);
    k_scan1<<<293, 256>>>();
    k_scan2<<<1, 512>>>();
    k_scan3<<<293, 256>>>();
    k_ptscatter_all<<<dim3((NPTS+255)/256, 3), 256>>>();
    k_slots0<<<262144/256, 256>>>();

    int pool_blocks = nrows[0] + nrows[1] + nrows[2];
    k_pool_all<<<pool_blocks, 128>>>(point_feat, vfs[0], vfs[1], vfs[2],
                                     pp[0], pp[1], pp[2]);
    int gemm_blocks = gm[0].nb + gm[1].nb + gm[2].nb;
    k_gemm_all<<<gemm_blocks, 256>>>(bs[0], bs[1], bs[2], out, gm[0], gm[1], gm[2]);
}

// round 9
// speedup vs baseline: 1.8044x; 1.1229x over previous
#include <cuda_runtime.h>
#include <stdint.h>

#define NPTS 120000
#define R0PAD 120064

// A (pre-split hi/lo) regions (u32 words)
#define OFF_L0 0ull
#define SZ_L0  (R0PAD*384ull)
#define OFF_L1 SZ_L0
#define SZ_L1  (32768ull*512ull)
#define OFF_L2 (OFF_L1 + SZ_L1)
#define SZ_L2  (4096ull*768ull)
#define VMAX_TOT (OFF_L2 + SZ_L2)

// Polar grid regions (ints)
#define GOFF0 0
#define GOFF1 691200
#define GOFF2 777600
#define GRID_TOT 788400

// Cartesian voxel-count regions (combined scan)
#define RO0 0
#define RO1 262144
#define RO2 294912
#define G_PAD 300032          // 293 * 1024

#define OUT_L0_F 33554432ull  // level-0 output floats to pre-zero

// GEMM double-buffer stage layout (u32 words)
#define STG_U32 9472          // Ah 2560 | Al 2560 | Bh 2176 | Bl 2176
#define GEMM_SMEM_B (2*STG_U32*4)

static __device__ unsigned g_Ah[VMAX_TOT];
static __device__ unsigned g_Al[VMAX_TOT];
static __device__ int      g_grid[GRID_TOT];
static __device__ int      g_p2p[3*NPTS];
static __device__ int      g_vox3[3*NPTS];
static __device__ int      g_pt[3*NPTS];
static __device__ int      g_cnts[G_PAD];
static __device__ int      g_start[G_PAD];
static __device__ int      g_cur[G_PAD];
static __device__ int      g_bsum[512];
static __device__ int      g_list[R0PAD];
static __device__ int      g_cnt;
static __device__ unsigned g_Wh[573440];
static __device__ unsigned g_Wl[573440];

struct KnnP  { int goff, P0, P1, P2; float pv0, pv1, pv2; };
struct GsP   { int M, goff, P0, P1, P2; };
struct CntP  { int ro, D0, D1, D2; float cv0, cv1, cv2; };
struct PoolP { unsigned long long voff; int ro, C, Kc, M, L, nrows, compact; };
struct GemmP { unsigned long long out_base, voff; int woff, ro, Kc, Nc, D0, D1, D2, nb, nxb, compact; };

__device__ __forceinline__ void split_tf32(float v, unsigned& hi, unsigned& lo){
    unsigned h; asm("cvt.rna.tf32.f32 %0, %1;" : "=r"(h) : "f"(v));
    float r = v - __uint_as_float(h);
    unsigned l; asm("cvt.rna.tf32.f32 %0, %1;" : "=r"(l) : "f"(r));
    hi = h; lo = l;
}
__device__ __forceinline__ void mma_tf32(float* d, const unsigned* a, const unsigned* b){
    asm volatile(
        "mma.sync.aligned.m16n8k8.row.col.f32.tf32.tf32.f32 "
        "{%0,%1,%2,%3}, {%4,%5,%6,%7}, {%8,%9}, {%0,%1,%2,%3};\n"
        : "+f"(d[0]), "+f"(d[1]), "+f"(d[2]), "+f"(d[3])
        : "r"(a[0]), "r"(a[1]), "r"(a[2]), "r"(a[3]), "r"(b[0]), "r"(b[1]));
}
__device__ __forceinline__ void cpa16(void* dst_smem, const void* src){
    unsigned d = (unsigned)__cvta_generic_to_shared(dst_smem);
    asm volatile("cp.async.cg.shared.global [%0], [%1], 16;" :: "r"(d), "l"(src));
}
__device__ __forceinline__ float4 max4(float4 a, float4 b){
    return make_float4(fmaxf(a.x,b.x), fmaxf(a.y,b.y), fmaxf(a.z,b.z), fmaxf(a.w,b.w));
}

// Prep: zero L0 output region; init polar grids, counts, slot counter.
// (g_Ah/g_Al rows for unoccupied voxels are never cleared: their GEMM output
// is forced to 0 by the occupancy mask and rows are accumulator-independent.)
__global__ void k_prep(float* __restrict__ out){
    const int no4 = (int)(OUT_L0_F >> 2);
    uint4 z = make_uint4(0u,0u,0u,0u);
    uint4* po = reinterpret_cast<uint4*>(out);
    int stride = gridDim.x*blockDim.x;
    int tid = blockIdx.x*blockDim.x + threadIdx.x;
    for (int i = tid; i < no4; i += stride) po[i] = z;
    for (int i = tid; i < GRID_TOT; i += stride) g_grid[i] = 0x7fffffff;
    for (int i = tid; i < G_PAD; i += stride) g_cnts[i] = 0;
    if (tid == 0) g_cnt = 0;
}

__global__ void k_splitW(const float* __restrict__ w0, const float* __restrict__ w1,
                         const float* __restrict__ w2){
    int stride = gridDim.x*blockDim.x;
    for (int i = blockIdx.x*blockDim.x + threadIdx.x; i < 573440; i += stride){
        float v;
        if (i < 49152)       v = w0[i];
        else if (i < 180224) v = w1[i - 49152];
        else                 v = w2[i - 180224];
        split_tf32(v, g_Wh[i], g_Wl[i]);
    }
}

__global__ void k_grid_scatter_all(const int* __restrict__ i0, const int* __restrict__ i1,
                                   const int* __restrict__ i2, GsP s0, GsP s1, GsP s2){
    int L = blockIdx.y;
    const int* idx = (L==0) ? i0 : (L==1) ? i1 : i2;
    GsP s = (L==0) ? s0 : (L==1) ? s1 : s2;
    int m = blockIdx.x*blockDim.x + threadIdx.x;
    if (m >= s.M) return;
    int x = idx[m*4+1], y = idx[m*4+2], z = idx[m*4+3];
    if ((unsigned)x >= (unsigned)s.P0 || (unsigned)y >= (unsigned)s.P1 ||
        (unsigned)z >= (unsigned)s.P2) return;
    atomicMin(&g_grid[s.goff + (x*s.P1+y)*s.P2 + z], m);
}

__device__ __forceinline__ void knn_check(const int* __restrict__ grid,
                                          int x,int y,int z,int qx,int qy,int qz,
                                          int P1,int P2,int& bd,int& bi){
    int c = grid[(x*P1+y)*P2 + z];
    if (c != 0x7fffffff){
        int dx = x-qx, dy = y-qy, dz = z-qz;
        int d = dx*dx + dy*dy + dz*dz;
        if (d < bd || (d == bd && c < bi)){ bd = d; bi = c; }
    }
}

// Exact 1-NN, 3 levels concurrent (integer distances < 2^24; first-index ties).
__global__ void k_knn_all(const float* __restrict__ pc, KnnP q0, KnnP q1, KnnP q2){
    int L = blockIdx.y;
    KnnP p = (L==0) ? q0 : (L==1) ? q1 : q2;
    int i = blockIdx.x*blockDim.x + threadIdx.x;
    if (i >= NPTS) return;
    const int* grid = g_grid + p.goff;
    int qx = (int)floorf(__fdiv_rn(pc[i*3+0]-0.0f,        p.pv0));
    int qy = (int)floorf(__fdiv_rn(pc[i*3+1]+3.14159274f, p.pv1));
    int qz = (int)floorf(__fdiv_rn(pc[i*3+2]+4.0f,        p.pv2));
    int bd = 0x7fffffff, bi = 0x7fffffff;
    int rmax = p.P0 + p.P1 + p.P2;
    for (int r = 0; r <= rmax; r++){
        if ((long long)r*r > (long long)bd) break;
        int x0 = max(qx-r, 0), x1 = min(qx+r, p.P0-1);
        int y0 = max(qy-r, 0), y1 = min(qy+r, p.P1-1);
        int z0 = max(qz-r, 0), z1 = min(qz+r, p.P2-1);
        for (int x = x0; x <= x1; x++){
            bool fx = (x == qx-r) || (x == qx+r);
            for (int y = y0; y <= y1; y++){
                bool fy = (y == qy-r) || (y == qy+r);
                if (fx | fy){
                    for (int z = z0; z <= z1; z++)
                        knn_check(grid,x,y,z,qx,qy,qz,p.P1,p.P2,bd,bi);
                } else {
                    int za = qz - r;
                    if (za >= 0 && za < p.P2) knn_check(grid,x,y,za,qx,qy,qz,p.P1,p.P2,bd,bi);
                    int zb = qz + r;
                    if (r > 0 && zb >= 0 && zb < p.P2) knn_check(grid,x,y,zb,qx,qy,qz,p.P1,p.P2,bd,bi);
                }
            }
        }
    }
    g_p2p[L*NPTS + i] = bi;
}

__global__ void k_count_all(const float* __restrict__ coord, CntP c0, CntP c1, CntP c2){
    int L = blockIdx.y;
    CntP c = (L==0) ? c0 : (L==1) ? c1 : c2;
    int i = blockIdx.x*blockDim.x + threadIdx.x;
    if (i >= NPTS) return;
    float fx = __fdiv_rn(coord[i*3+0] + 25.6f, c.cv0);
    float fy = __fdiv_rn(coord[i*3+1] + 25.6f, c.cv1);
    float fz = __fdiv_rn(coord[i*3+2] + 2.0f,  c.cv2);
    int x = min(max((int)floorf(fx), 0), c.D0-1);
    int y = min(max((int)floorf(fy), 0), c.D1-1);
    int z = min(max((int)floorf(fz), 0), c.D2-1);
    int lin = (x*c.D2 + z)*c.D1 + y;       // internal ordering: y fastest
    g_vox3[L*NPTS + i] = lin;
    atomicAdd(&g_cnts[c.ro + lin], 1);
}

__global__ void k_scan1(){
    __shared__ int sh[256];
    int b = blockIdx.x, t = threadIdx.x;
    int base = b*1024 + t*4;
    int4 v = *reinterpret_cast<int4*>(&g_cnts[base]);
    int s = v.x+v.y+v.z+v.w;
    sh[t] = s;
    __syncthreads();
    #pragma unroll
    for (int off = 1; off < 256; off <<= 1){
        int val = (t >= off) ? sh[t-off] : 0;
        __syncthreads();
        sh[t] += val;
        __syncthreads();
    }
    int excl = sh[t] - s;
    g_start[base]   = excl;
    g_start[base+1] = excl + v.x;
    g_start[base+2] = excl + v.x + v.y;
    g_start[base+3] = excl + v.x + v.y + v.z;
    if (t == 255) g_bsum[b] = sh[255];
}
__global__ void k_scan2(){
    __shared__ int sh[512];
    int t = threadIdx.x;
    int v = (t < 293) ? g_bsum[t] : 0;
    sh[t] = v;
    __syncthreads();
    #pragma unroll
    for (int off = 1; off < 512; off <<= 1){
        int x = (t >= off) ? sh[t-off] : 0;
        __syncthreads();
        sh[t] += x;
        __syncthreads();
    }
    if (t < 293) g_bsum[t] = sh[t] - v;   // exclusive
}
__global__ void k_scan3(){
    int b = blockIdx.x, t = threadIdx.x;
    int add = g_bsum[b];
    int base = b*1024 + t*4;
    int4 v = *reinterpret_cast<int4*>(&g_start[base]);
    v.x += add; v.y += add; v.z += add; v.w += add;
    *reinterpret_cast<int4*>(&g_start[base]) = v;
    *reinterpret_cast<int4*>(&g_cur[base])   = v;
}

__global__ void k_ptscatter_all(){
    int L = blockIdx.y;
    int ro = (L==0) ? RO0 : (L==1) ? RO1 : RO2;
    int i = blockIdx.x*blockDim.x + threadIdx.x;
    if (i >= NPTS) return;
    int lin = g_vox3[L*NPTS + i];
    int pos = atomicAdd(&g_cur[ro + lin], 1);
    g_pt[pos] = i;
}

__global__ void k_slots0(){
    int lin = blockIdx.x*blockDim.x + threadIdx.x;
    if (lin >= 262144) return;
    if (g_cnts[RO0 + lin] > 0){
        int slot = atomicAdd(&g_cnt, 1);
        g_list[slot] = lin;
    }
}

// Gather-based max pooling, ALL levels in one launch; float4 channel groups,
// 2-point unroll; output written PRE-SPLIT (tf32 hi/lo) for the GEMM.
__global__ void __launch_bounds__(128)
k_pool_all(const float* __restrict__ pf,
           const float* __restrict__ vf0, const float* __restrict__ vf1,
           const float* __restrict__ vf2,
           PoolP p0, PoolP p1, PoolP p2){
    int b = blockIdx.x;
    PoolP p; const float* vf;
    if (b < p0.nrows){ p = p0; vf = vf0; }
    else if (b < p0.nrows + p1.nrows){ p = p1; vf = vf1; b -= p0.nrows; }
    else { p = p2; vf = vf2; b -= p0.nrows + p1.nrows; }
    int row = b, lin;
    if (p.compact){
        if (row >= g_cnt) return;
        lin = g_list[row];
    } else lin = row;
    int s0 = g_start[p.ro + lin], s1 = g_start[p.ro + lin + 1];
    int n = s1 - s0;
    if (n <= 0) return;
    __shared__ int sp[128], spp[128];
    int t = threadIdx.x;
    const float4* pf4 = reinterpret_cast<const float4*>(pf);
    const float4* vf4 = reinterpret_cast<const float4*>(vf);
    int C4 = p.C >> 2;
    int K4 = p.Kc >> 2;                    // 96 / 128 / 192
    float4 m[2];
    float ninf = -__int_as_float(0x7f800000);
    m[0] = make_float4(ninf, ninf, ninf, ninf);
    m[1] = m[0];
    for (int c0 = 0; c0 < n; c0 += 128){
        int nc = min(128, n - c0);
        __syncthreads();
        if (t < nc){
            int i = g_pt[s0 + c0 + t];
            sp[t] = i;
            int pp = g_p2p[p.L*NPTS + i];
            spp[t] = ((unsigned)pp < (unsigned)p.M) ? pp : 0;
        }
        __syncthreads();
        int j = 0;
        for (; j + 2 <= nc; j += 2){
            int ia = sp[j],   pa = spp[j];
            int ib = sp[j+1], pb = spp[j+1];
            int q = 0;
            for (int kq = t; kq < K4; kq += 128, q++){
                float4 a = (kq < 64) ? pf4[(size_t)ia*64 + kq]
                                     : vf4[(size_t)pa*C4 + (kq-64)];
                float4 c = (kq < 64) ? pf4[(size_t)ib*64 + kq]
                                     : vf4[(size_t)pb*C4 + (kq-64)];
                m[q] = max4(m[q], max4(a, c));
            }
        }
        if (j < nc){
            int ia = sp[j], pa = spp[j];
            int q = 0;
            for (int kq = t; kq < K4; kq += 128, q++){
                float4 a = (kq < 64) ? pf4[(size_t)ia*64 + kq]
                                     : vf4[(size_t)pa*C4 + (kq-64)];
                m[q] = max4(m[q], a);
            }
        }
    }
    size_t rb = p.voff + (size_t)row * (size_t)p.Kc;
    int q = 0;
    for (int kq = t; kq < K4; kq += 128, q++){
        float4 v = m[q];
        uint4 h, l;
        split_tf32(v.x, h.x, l.x);
        split_tf32(v.y, h.y, l.y);
        split_tf32(v.z, h.z, l.z);
        split_tf32(v.w, h.w, l.w);
        *reinterpret_cast<uint4*>(&g_Ah[rb + kq*4]) = h;
        *reinterpret_cast<uint4*>(&g_Al[rb + kq*4]) = l;
    }
}

// Split-TF32 tensor-core GEMM, ALL levels in one launch, cp.async
// double-buffered. out = relu(A @ W + b), occupancy-masked, stored in
// [C*D2, D0, D1] layout. A pre-split row-major (smem stride 20/16-k tile);
// B pre-split [k][n] (smem stride 136). Both fragment patterns bank-conflict-free.
__global__ void __launch_bounds__(256, 2)
k_gemm_all(const float* __restrict__ b0, const float* __restrict__ b1,
           const float* __restrict__ b2, float* __restrict__ out,
           GemmP q0, GemmP q1, GemmP q2){
    extern __shared__ unsigned dyn[];
    int b = blockIdx.x;
    GemmP p; const float* bias;
    if (b < q0.nb){ p = q0; bias = b0; }
    else if (b < q0.nb + q1.nb){ p = q1; bias = b1; b -= q0.nb; }
    else { p = q2; bias = b2; b -= q0.nb + q1.nb; }
    int bx = b % p.nxb, by = b / p.nxb;
    int row0 = bx * 128;
    int cnt = 0;
    if (p.compact){
        cnt = *(volatile int*)&g_cnt;
        if (row0 >= cnt) return;
    }
    __shared__ int s_ob[128];
    __shared__ int s_oc[128];

    int t = threadIdx.x;
    int lane = t & 31, wid = t >> 5;
    int warp_m = wid & 1, warp_n = wid >> 1;
    int g = lane >> 2, tg = lane & 3;
    int col0 = by * 128;
    const unsigned* gAh = g_Ah + p.voff + (size_t)row0 * (size_t)p.Kc;
    const unsigned* gAl = g_Al + p.voff + (size_t)row0 * (size_t)p.Kc;
    const unsigned* Whb = g_Wh + p.woff;
    const unsigned* Wlb = g_Wl + p.woff;
    int niter = p.Kc >> 4;

    // stage s pointers
    auto stage_fill = [&](int s, int k0){
        unsigned* S  = dyn + s*STG_U32;
        unsigned* Ah = S;
        unsigned* Al = S + 2560;
        unsigned* Bh = S + 5120;
        unsigned* Bl = S + 7296;
        #pragma unroll
        for (int j = 0; j < 2; j++){
            int seg = t + j*256;               // 0..511
            int m   = seg >> 2;
            int si  = (seg & 3) << 2;          // k sub-offset 0,4,8,12
            size_t go = (size_t)m*p.Kc + k0 + si;
            cpa16(Ah + m*20 + si, gAh + go);
            cpa16(Al + m*20 + si, gAl + go);
        }
        #pragma unroll
        for (int j = 0; j < 2; j++){
            int seg = t + j*256;               // 0..511
            int kk  = seg >> 5;                // 0..15
            int n4  = (seg & 31) << 2;         // 0..124
            size_t go = (size_t)(k0+kk)*p.Nc + col0 + n4;
            cpa16(Bh + kk*136 + n4, Whb + go);
            cpa16(Bl + kk*136 + n4, Wlb + go);
        }
    };

    float acc[4][4][4];
    #pragma unroll
    for (int a = 0; a < 4; a++)
        #pragma unroll
        for (int c = 0; c < 4; c++)
            #pragma unroll
            for (int d = 0; d < 4; d++) acc[a][c][d] = 0.0f;

    stage_fill(0, 0);
    asm volatile("cp.async.commit_group;");

    for (int it = 0; it < niter; it++){
        int nxt = it + 1;
        if (nxt < niter) stage_fill(nxt & 1, nxt << 4);
        asm volatile("cp.async.commit_group;");
        asm volatile("cp.async.wait_group 1;");
        __syncthreads();

        unsigned* S  = dyn + (it & 1)*STG_U32;
        unsigned* Ah = S;
        unsigned* Al = S + 2560;
        unsigned* Bh = S + 5120;
        unsigned* Bl = S + 7296;
        #pragma unroll
        for (int ks = 0; ks < 2; ks++){
            int kk = ks << 3;
            unsigned bhf[4][2], blf[4][2];
            #pragma unroll
            for (int nt = 0; nt < 4; nt++){
                int n = warp_n*32 + nt*8 + g;
                bhf[nt][0] = Bh[(kk+tg)*136 + n];
                bhf[nt][1] = Bh[(kk+tg+4)*136 + n];
                blf[nt][0] = Bl[(kk+tg)*136 + n];
                blf[nt][1] = Bl[(kk+tg+4)*136 + n];
            }
            #pragma unroll
            for (int mt = 0; mt < 4; mt++){
                int r0 = warp_m*64 + mt*16 + g;
                unsigned ahf[4], alf[4];
                ahf[0] = Ah[(r0  )*20 + kk+tg];
                ahf[1] = Ah[(r0+8)*20 + kk+tg];
                ahf[2] = Ah[(r0  )*20 + kk+tg+4];
                ahf[3] = Ah[(r0+8)*20 + kk+tg+4];
                alf[0] = Al[(r0  )*20 + kk+tg];
                alf[1] = Al[(r0+8)*20 + kk+tg];
                alf[2] = Al[(r0  )*20 + kk+tg+4];
                alf[3] = Al[(r0+8)*20 + kk+tg+4];
                #pragma unroll
                for (int nt = 0; nt < 4; nt++){
                    mma_tf32(acc[mt][nt], ahf, bhf[nt]);
                    mma_tf32(acc[mt][nt], ahf, blf[nt]);
                    mma_tf32(acc[mt][nt], alf, bhf[nt]);
                }
            }
        }
        __syncthreads();
    }

    if (t < 128){
        int v = row0 + t;
        int lin = p.compact ? g_list[v] : v;
        int y  = lin % p.D1;
        int q  = lin / p.D1;
        int zz = q % p.D2;
        int xx = q / p.D2;
        s_ob[t] = (zz*p.D0 + xx)*p.D1 + y;
        s_oc[t] = p.compact ? (v < cnt) : (g_cnts[p.ro + v] > 0);
    }
    __syncthreads();

    size_t cstride = (size_t)p.D2 * p.D0 * p.D1;
    float* stage = reinterpret_cast<float*>(dyn);   // 32 x 128, stride 132
    #pragma unroll
    for (int s = 0; s < 4; s++){
        if (warp_n == s){
            #pragma unroll
            for (int mt = 0; mt < 4; mt++){
                int r0 = warp_m*64 + mt*16 + g;
                int r1 = r0 + 8;
                int oc0 = s_oc[r0], oc1 = s_oc[r1];
                #pragma unroll
                for (int nt = 0; nt < 4; nt++){
                    int cb = nt*8 + 2*tg;
                    float bv0 = bias[col0 + s*32 + cb];
                    float bv1 = bias[col0 + s*32 + cb + 1];
                    stage[(cb  )*132 + r0] = oc0 ? fmaxf(acc[mt][nt][0] + bv0, 0.0f) : 0.0f;
                    stage[(cb+1)*132 + r0] = oc0 ? fmaxf(acc[mt][nt][1] + bv1, 0.0f) : 0.0f;
                    stage[(cb  )*132 + r1] = oc1 ? fmaxf(acc[mt][nt][2] + bv0, 0.0f) : 0.0f;
                    stage[(cb+1)*132 + r1] = oc1 ? fmaxf(acc[mt][nt][3] + bv1, 0.0f) : 0.0f;
                }
            }
        }
        __syncthreads();
        #pragma unroll
        for (int j = 0; j < 16; j++){
            int e  = t + j*256;
            int cc = e >> 7;
            int rr = e & 127;
            int c  = col0 + (s << 5) + cc;
            if (!p.compact || s_oc[rr])
                out[p.out_base + (size_t)c*cstride + s_ob[rr]] = stage[cc*132 + rr];
        }
        __syncthreads();
    }
}

extern "C" void kernel_launch(void* const* d_in, const int* in_sizes, int n_in,
                              void* d_out, int out_size){
    (void)in_sizes; (void)n_in; (void)out_size;
    const float* point_feat = (const float*)d_in[0];
    const float* p_coord    = (const float*)d_in[1];
    const float* coord      = (const float*)d_in[2];
    const int*   idxs[3] = {(const int*)d_in[4],  (const int*)d_in[8],  (const int*)d_in[12]};
    const float* vfs[3]  = {(const float*)d_in[5],(const float*)d_in[9],(const float*)d_in[13]};
    const float* Ws[3]   = {(const float*)d_in[6],(const float*)d_in[10],(const float*)d_in[14]};
    const float* bs[3]   = {(const float*)d_in[7],(const float*)d_in[11],(const float*)d_in[15]};
    float* out = (float*)d_out;

    const int Ms[3]  = {40000, 15000, 5000};
    const int Cs[3]  = {128, 256, 512};
    const int P0s[3] = {240, 120, 60}, P1s[3] = {180, 90, 45}, P2s[3] = {16, 8, 4};
    const int D0s[3] = {128, 64, 32},  D1s[3] = {128, 64, 32}, D2s[3] = {16, 8, 4};
    const int goffs[3] = {GOFF0, GOFF1, GOFF2};
    const int ros[3]   = {RO0, RO1, RO2};
    const int woffs[3] = {0, 49152, 180224};
    const size_t voffs[3] = {OFF_L0, OFF_L1, OFF_L2};
    const int nrows[3] = {R0PAD, 32768, 4096};

    const float pi  = 3.14159265358979f;
    const float r0c = 50.0f, r1c = pi + pi, r2c = 6.0f;
    const float cr0 = 25.6f + 25.6f, cr1 = cr0, cr2 = 4.4f + 2.0f;

    KnnP kp[3]; GsP gp[3]; CntP cp[3]; PoolP pp[3]; GemmP gm[3];
    size_t base = 0;
    for (int L = 0; L < 3; L++){
        float sf = (float)(2 << L);
        kp[L].goff = goffs[L];
        kp[L].P0 = P0s[L]; kp[L].P1 = P1s[L]; kp[L].P2 = P2s[L];
        kp[L].pv0 = r0c / (479.0f / sf);
        kp[L].pv1 = r1c / (359.0f / sf);
        kp[L].pv2 = r2c / (31.0f  / sf);
        gp[L].M = Ms[L]; gp[L].goff = goffs[L];
        gp[L].P0 = P0s[L]; gp[L].P1 = P1s[L]; gp[L].P2 = P2s[L];
        cp[L].ro = ros[L];
        cp[L].D0 = D0s[L]; cp[L].D1 = D1s[L]; cp[L].D2 = D2s[L];
        cp[L].cv0 = cr0 / (float)D0s[L];
        cp[L].cv1 = cr1 / (float)D1s[L];
        cp[L].cv2 = cr2 / (float)D2s[L];
        pp[L].voff = voffs[L]; pp[L].ro = ros[L];
        pp[L].C = Cs[L]; pp[L].Kc = 256 + Cs[L]; pp[L].M = Ms[L];
        pp[L].L = L; pp[L].nrows = nrows[L]; pp[L].compact = (L == 0);
        gm[L].out_base = base; gm[L].voff = voffs[L];
        gm[L].woff = woffs[L]; gm[L].ro = ros[L];
        gm[L].Kc = 256 + Cs[L]; gm[L].Nc = Cs[L];
        gm[L].D0 = D0s[L]; gm[L].D1 = D1s[L]; gm[L].D2 = D2s[L];
        gm[L].nxb = nrows[L] / 128;
        gm[L].nb  = gm[L].nxb * (Cs[L] / 128);
        gm[L].compact = (L == 0);
        base += (size_t)Cs[L] * D2s[L] * D0s[L] * D1s[L];
    }

    cudaFuncSetAttribute(k_gemm_all, cudaFuncAttributeMaxDynamicSharedMemorySize,
                         GEMM_SMEM_B);

    k_prep<<<1024, 256>>>(out);
    k_splitW<<<560, 256>>>(Ws[0], Ws[1], Ws[2]);
    k_grid_scatter_all<<<dim3((Ms[0]+255)/256, 3), 256>>>(idxs[0], idxs[1], idxs[2],
                                                          gp[0], gp[1], gp[2]);
    k_knn_all<<<dim3((NPTS+127)/128, 3), 128>>>(p_coord, kp[0], kp[1], kp[2]);
    k_count_all<<<dim3((NPTS+255)/256, 3), 256>>>(coord, cp[0], cp[1], cp[2]);
    k_scan1<<<293, 256>>>();
    k_scan2<<<1, 512>>>();
    k_scan3<<<293, 256>>>();
    k_ptscatter_all<<<dim3((NPTS+255)/256, 3), 256>>>();
    k_slots0<<<262144/256, 256>>>();

    int pool_blocks = nrows[0] + nrows[1] + nrows[2];
    k_pool_all<<<pool_blocks, 128>>>(point_feat, vfs[0], vfs[1], vfs[2],
                                     pp[0], pp[1], pp[2]);
    int gemm_blocks = gm[0].nb + gm[1].nb + gm[2].nb;
    k_gemm_all<<<gemm_blocks, 256, GEMM_SMEM_B>>>(bs[0], bs[1], bs[2], out,
                                                  gm[0], gm[1], gm[2]);
}